// round 11
// baseline (speedup 1.0000x reference)
#include <cuda_runtime.h>
#include <cuda_bf16.h>
#include <cstdint>

// ---------------------------------------------------------------------------
// MultiHeadAttention (B=4, S=2048, E=1024, H=16, hd=64), fp32 in/out.
// All heavy math on legacy tensor path (mma.sync.m16n8k16 bf16) with 3-term
// hi/lo splits for fp32-level accuracy:
//   GEMMs: A3=[ah|ah|al], B3=[bh|bl|bh] packed along K (K'=3072)
//   Flash: S = qh.kh + qh.kl + ql.kh ; O += ph.vh + ph.vl + pl.vh
// R7: hgemm retiled to 4 warps x (64x64) per 128x128 CTA (LDSM:MMA 1:4).
// ---------------------------------------------------------------------------

#define C_S   2048
#define C_E   1024
#define C_3E  3072
#define C_H   16
#define C_TOK 8192
#define K3    3072
#define KC    32
#define NCH   (K3/KC)   // 96
#define NSTAGE 4

// ---------------- common helpers ----------------
__device__ __forceinline__ uint32_t smem_u32(const void* p) {
    uint32_t a;
    asm("{ .reg .u64 t; cvta.to.shared.u64 t, %1; cvt.u32.u64 %0, t; }" : "=r"(a) : "l"(p));
    return a;
}
__device__ __forceinline__ void cpa16(uint32_t s, const void* g) {
    asm volatile("cp.async.cg.shared.global [%0], [%1], 16;" :: "r"(s), "l"(g));
}
#define CP_COMMIT() asm volatile("cp.async.commit_group;" ::: "memory")
#define CP_WAIT(n)  asm volatile("cp.async.wait_group %0;" :: "n"(n) : "memory")
#define LDSM_X4(r0,r1,r2,r3,addr) \
    asm volatile("ldmatrix.sync.aligned.m8n8.x4.shared.b16 {%0,%1,%2,%3}, [%4];" \
                 : "=r"(r0),"=r"(r1),"=r"(r2),"=r"(r3) : "r"(addr))
#define LDSM_X4T(r0,r1,r2,r3,addr) \
    asm volatile("ldmatrix.sync.aligned.m8n8.x4.trans.shared.b16 {%0,%1,%2,%3}, [%4];" \
                 : "=r"(r0),"=r"(r1),"=r"(r2),"=r"(r3) : "r"(addr))
#define MMA16816(d, a, b) \
    asm volatile("mma.sync.aligned.m16n8k16.row.col.f32.bf16.bf16.f32 " \
                 "{%0,%1,%2,%3},{%4,%5,%6,%7},{%8,%9},{%0,%1,%2,%3};" \
                 : "+f"((d)[0]),"+f"((d)[1]),"+f"((d)[2]),"+f"((d)[3]) \
                 : "r"((a)[0]),"r"((a)[1]),"r"((a)[2]),"r"((a)[3]), \
                   "r"((b)[0]),"r"((b)[1]))

__device__ __forceinline__ uint32_t pkbf2(float a, float b) {
    __nv_bfloat162 h = __floats2bfloat162_rn(a, b);
    return *reinterpret_cast<uint32_t*>(&h);
}
__device__ __forceinline__ void bsplit2(float a, float b, uint32_t& hi, uint32_t& lo) {
    const __nv_bfloat16 ah = __float2bfloat16_rn(a);
    const __nv_bfloat16 bh = __float2bfloat16_rn(b);
    __nv_bfloat162 hp; hp.x = ah; hp.y = bh;
    hi = *reinterpret_cast<uint32_t*>(&hp);
    lo = pkbf2(a - __bfloat162float(ah), b - __bfloat162float(bh));
}

// ---------------- device-global scratch ----------------
__device__ float          g_qkv[(size_t)C_TOK * C_3E];
__device__ __nv_bfloat16  g_x3[(size_t)C_TOK * K3];
__device__ __nv_bfloat16  g_a3[(size_t)C_TOK * K3];
__device__ __nv_bfloat16  g_wa3[(size_t)C_3E * K3];
__device__ __nv_bfloat16  g_wp3[(size_t)C_E * K3];

// ---------------------------------------------------------------------------
// split-pack x: fp32 [M][1024] -> bf16 [M][3072] = [ah | ah | al]
// ---------------------------------------------------------------------------
__global__ __launch_bounds__(256)
void split_pack_kernel(const float* __restrict__ in, __nv_bfloat16* __restrict__ o3)
{
    const int i4 = blockIdx.x * 256 + threadIdx.x;
    const int m  = i4 >> 8;
    const int kq = i4 & 255;
    const float4 v = *(const float4*)(in + (size_t)m * C_E + kq * 4);
    uint32_t h0, l0, h1, l1;
    bsplit2(v.x, v.y, h0, l0);
    bsplit2(v.z, v.w, h1, l1);
    uint2 hh = make_uint2(h0, h1);
    uint2 ll = make_uint2(l0, l1);
    __nv_bfloat16* base = o3 + (size_t)m * K3 + kq * 4;
    *(uint2*)(base)          = hh;
    *(uint2*)(base + C_E)    = hh;
    *(uint2*)(base + 2*C_E)  = ll;
}

// ---------------------------------------------------------------------------
// transpose + split-pack W[K=1024][N] -> Wt3[N][3072] = [bh | bl | bh]
// ---------------------------------------------------------------------------
__global__ __launch_bounds__(256)
void transpose_pack_kernel(const float* __restrict__ W, __nv_bfloat16* __restrict__ T3, int N)
{
    __shared__ float t[32][33];
    const int tx = threadIdx.x, ty = threadIdx.y;
    const int n0 = blockIdx.x * 32, k0 = blockIdx.y * 32;
    #pragma unroll
    for (int i = 0; i < 4; i++)
        t[ty + i * 8][tx] = W[(size_t)(k0 + ty + i * 8) * N + n0 + tx];
    __syncthreads();
    #pragma unroll
    for (int i = 0; i < 4; i++) {
        const float v = t[tx][ty + i * 8];
        const __nv_bfloat16 bh = __float2bfloat16_rn(v);
        const __nv_bfloat16 bl = __float2bfloat16_rn(v - __bfloat162float(bh));
        __nv_bfloat16* base = T3 + (size_t)(n0 + ty + i * 8) * K3 + k0 + tx;
        base[0]       = bh;
        base[C_E]     = bl;
        base[2*C_E]   = bh;
    }
}

// ---------------------------------------------------------------------------
// bf16 HGEMM: C = A3 @ B3^T + bias. CTA 128x128, 4 warps x (64x64) warp tiles,
// K-chunk 32, 4-stage cp.async pipeline, ONE __syncthreads per chunk.
// smem row = 64B (4x16B chunks), chunk cc stored at cc^(r&3).
// ---------------------------------------------------------------------------
__global__ __launch_bounds__(128)
void hgemm_bf16_kernel(const __nv_bfloat16* __restrict__ A3,
                       const __nv_bfloat16* __restrict__ B3,
                       const float* __restrict__ bias,
                       float* __restrict__ C, int N)
{
    extern __shared__ __align__(16) unsigned char dsm[];
    // A stages: [0, 32KB), B stages: [32KB, 64KB); 8KB per stage each
    __shared__ float bias_s[128];

    const int t    = threadIdx.x;
    const int lane = t & 31;
    const int wid  = t >> 5;
    const int bm   = blockIdx.y * 128;
    const int bn   = blockIdx.x * 128;
    const int wm   = (wid & 1) * 64;
    const int wn   = (wid >> 1) * 64;

    bias_s[t] = bias[bn + t];

    const uint32_t sa = smem_u32(dsm);
    const uint32_t sb = sa + 32768u;

    // ---- fill mapping: each thread owns one full 64B row of A and of B
    const int fr = t;                        // row 0..127
    uint32_t so[4];
    #pragma unroll
    for (int cc = 0; cc < 4; cc++)
        so[cc] = (uint32_t)fr * 64u + (uint32_t)((cc ^ (fr & 3)) << 4);
    const __nv_bfloat16* gA = A3 + (size_t)(bm + fr) * K3;
    const __nv_bfloat16* gB = B3 + (size_t)(bn + fr) * K3;

    // ---- ldmatrix per-lane address precompute
    const int lr = lane & 7;
    const int ccA = (lane >> 4) & 1;         // k-chunk bit for A tiles
    const int ahalf = (lane >> 3) & 1;       // m 8-row half
    const int ccB = (lane >> 3) & 1;         // k-chunk bit for B tiles
    const int bhalf = (lane >> 4) & 1;       // n 8-row half
    uint32_t offA[4]; int rm3A[4];
    #pragma unroll
    for (int i = 0; i < 4; i++) {
        const int r = wm + i * 16 + ahalf * 8 + lr;
        offA[i] = (uint32_t)r * 64u; rm3A[i] = r & 3;
    }
    uint32_t offB[4]; int rm3B[4];
    #pragma unroll
    for (int j = 0; j < 4; j++) {
        const int r = wn + j * 16 + bhalf * 8 + lr;
        offB[j] = (uint32_t)r * 64u; rm3B[j] = r & 3;
    }

    float acc[4][8][4];
    #pragma unroll
    for (int i = 0; i < 4; i++)
        #pragma unroll
        for (int n = 0; n < 8; n++)
            #pragma unroll
            for (int k = 0; k < 4; k++) acc[i][n][k] = 0.f;

    // prologue: stages 0..2
    #pragma unroll
    for (int p = 0; p < NSTAGE - 1; p++) {
        const uint32_t d = (uint32_t)p * 8192u;
        #pragma unroll
        for (int cc = 0; cc < 4; cc++) {
            cpa16(sa + d + so[cc], gA + p * KC + cc * 8);
            cpa16(sb + d + so[cc], gB + p * KC + cc * 8);
        }
        CP_COMMIT();
    }

    for (int c = 0; c < NCH; c++) {
        CP_WAIT(NSTAGE - 2);
        __syncthreads();
        if (c + NSTAGE - 1 < NCH) {
            const uint32_t d = (uint32_t)((c + NSTAGE - 1) & (NSTAGE - 1)) * 8192u;
            #pragma unroll
            for (int cc = 0; cc < 4; cc++) {
                cpa16(sa + d + so[cc], gA + (c + NSTAGE - 1) * KC + cc * 8);
                cpa16(sb + d + so[cc], gB + (c + NSTAGE - 1) * KC + cc * 8);
            }
        }
        CP_COMMIT();   // empty group in tail keeps wait_group accounting exact

        const uint32_t ab = sa + (uint32_t)(c & (NSTAGE - 1)) * 8192u;
        const uint32_t bb = sb + (uint32_t)(c & (NSTAGE - 1)) * 8192u;
        #pragma unroll
        for (int s = 0; s < 2; s++) {
            uint32_t a[4][4];
            #pragma unroll
            for (int i = 0; i < 4; i++) {
                const uint32_t addr = ab + offA[i] +
                    (uint32_t)((((s << 1) | ccA) ^ rm3A[i]) << 4);
                LDSM_X4(a[i][0], a[i][1], a[i][2], a[i][3], addr);
            }
            uint32_t bfr[8][2];
            #pragma unroll
            for (int j = 0; j < 4; j++) {
                const uint32_t addr = bb + offB[j] +
                    (uint32_t)((((s << 1) | ccB) ^ rm3B[j]) << 4);
                uint32_t r0, r1, r2, r3;
                LDSM_X4(r0, r1, r2, r3, addr);
                bfr[2 * j][0] = r0;     bfr[2 * j][1] = r1;
                bfr[2 * j + 1][0] = r2; bfr[2 * j + 1][1] = r3;
            }
            #pragma unroll
            for (int i = 0; i < 4; i++)
                #pragma unroll
                for (int n = 0; n < 8; n++)
                    MMA16816(acc[i][n], a[i], bfr[n]);
        }
    }

    __syncthreads();
    #pragma unroll
    for (int i = 0; i < 4; i++) {
        const int row0 = bm + wm + i * 16 + (lane >> 2);
        #pragma unroll
        for (int n = 0; n < 8; n++) {
            const int lcol = wn + n * 8 + (lane & 3) * 2;
            const int col  = bn + lcol;
            const float b0 = bias_s[lcol], b1 = bias_s[lcol + 1];
            float2 v0 = make_float2(acc[i][n][0] + b0, acc[i][n][1] + b1);
            float2 v1 = make_float2(acc[i][n][2] + b0, acc[i][n][3] + b1);
            *(float2*)(C + (size_t)row0 * N + col)       = v0;
            *(float2*)(C + (size_t)(row0 + 8) * N + col) = v1;
        }
    }
}

// ---------------------------------------------------------------------------
// Flash attention on tensor cores (FA2-style). Block = 128 thr (4 warps),
// each warp owns 16 q-rows of a 64-row q-tile. hi/lo bf16 splits everywhere.
// K is B-operand directly ([j][d] rows); V via ldmatrix.trans; P stays in regs.
// smem rows = 128B (8 chunks), chunk cc stored at cc^(r&7).
// ---------------------------------------------------------------------------
__global__ __launch_bounds__(128, 3)
void flash_mma_kernel(const float* __restrict__ qkv, __nv_bfloat16* __restrict__ a3)
{
    __shared__ __align__(16) __nv_bfloat16 sQh[64 * 64], sQl[64 * 64];
    __shared__ __align__(16) __nv_bfloat16 sKh[64 * 64], sKl[64 * 64];
    __shared__ __align__(16) __nv_bfloat16 sVh[64 * 64], sVl[64 * 64];

    const int qt  = (int)gridDim.x - 1 - (int)blockIdx.x;
    const int bh  = blockIdx.y;
    const int b   = bh >> 4;
    const int h   = bh & 15;
    const int tid = threadIdx.x;
    const int lane = tid & 31;
    const int wq   = tid >> 5;           // warp q-row block: rows wq*16..+15

    const float* Qg = qkv + (size_t)b * C_S * C_3E + h * 64;
    const float* Kg = Qg + C_E;
    const float* Vg = Qg + 2 * C_E;

    const uint32_t bQh = smem_u32(sQh), bQl = smem_u32(sQl);
    const uint32_t bKh = smem_u32(sKh), bKl = smem_u32(sKl);
    const uint32_t bVh = smem_u32(sVh), bVl = smem_u32(sVl);

    // ---- load Q tile, split to hi/lo smem (64 rows x 8 chunks of 16B)
    #pragma unroll
    for (int it = 0; it < 4; it++) {
        const int ch = it * 128 + tid;
        const int r  = ch >> 3;
        const int cc = ch & 7;
        const float* src = Qg + (size_t)(qt * 64 + r) * C_3E + cc * 8;
        const float4 u = *(const float4*)src;
        const float4 w = *(const float4*)(src + 4);
        uint4 hi, lo;
        bsplit2(u.x, u.y, hi.x, lo.x);
        bsplit2(u.z, u.w, hi.y, lo.y);
        bsplit2(w.x, w.y, hi.z, lo.z);
        bsplit2(w.z, w.w, hi.w, lo.w);
        const uint32_t off = r * 128u + (uint32_t)((cc ^ (r & 7)) << 4);
        *(uint4*)((char*)sQh + off) = hi;
        *(uint4*)((char*)sQl + off) = lo;
    }
    __syncthreads();

    // ---- build Q A-fragments in registers (persist whole kernel)
    uint32_t qhf[4][4], qlf[4][4];
    {
        const int arow = wq * 16 + ((lane >> 3) & 1) * 8 + (lane & 7);
        const uint32_t ro = (uint32_t)arow * 128u;
        const int rm = arow & 7;
        const int cca = (lane >> 4) & 1;
        #pragma unroll
        for (int ks = 0; ks < 4; ks++) {
            const uint32_t co = (uint32_t)(((ks * 2 + cca) ^ rm) << 4);
            LDSM_X4(qhf[ks][0], qhf[ks][1], qhf[ks][2], qhf[ks][3], bQh + ro + co);
            LDSM_X4(qlf[ks][0], qlf[ks][1], qlf[ks][2], qlf[ks][3], bQl + ro + co);
        }
    }

    const int g  = lane >> 2;
    const int qq = lane & 3;
    float m0 = -1e30f, m1 = -1e30f, l0 = 0.f, l1 = 0.f;
    float O[8][4];
    #pragma unroll
    for (int dt = 0; dt < 8; dt++)
        #pragma unroll
        for (int k = 0; k < 4; k++) O[dt][k] = 0.f;

    for (int kt = 0; kt <= qt; kt++) {
        __syncthreads();   // prior iteration's ldmatrix reads of K/V done
        // ---- load K and V tiles, split to hi/lo smem
        #pragma unroll
        for (int it = 0; it < 4; it++) {
            const int ch = it * 128 + tid;
            const int r  = ch >> 3;
            const int cc = ch & 7;
            const uint32_t off = r * 128u + (uint32_t)((cc ^ (r & 7)) << 4);
            {
                const float* src = Kg + (size_t)(kt * 64 + r) * C_3E + cc * 8;
                const float4 u = *(const float4*)src;
                const float4 w = *(const float4*)(src + 4);
                uint4 hi, lo;
                bsplit2(u.x, u.y, hi.x, lo.x);
                bsplit2(u.z, u.w, hi.y, lo.y);
                bsplit2(w.x, w.y, hi.z, lo.z);
                bsplit2(w.z, w.w, hi.w, lo.w);
                *(uint4*)((char*)sKh + off) = hi;
                *(uint4*)((char*)sKl + off) = lo;
            }
            {
                const float* src = Vg + (size_t)(kt * 64 + r) * C_3E + cc * 8;
                const float4 u = *(const float4*)src;
                const float4 w = *(const float4*)(src + 4);
                uint4 hi, lo;
                bsplit2(u.x, u.y, hi.x, lo.x);
                bsplit2(u.z, u.w, hi.y, lo.y);
                bsplit2(w.x, w.y, hi.z, lo.z);
                bsplit2(w.z, w.w, hi.w, lo.w);
                *(uint4*)((char*)sVh + off) = hi;
                *(uint4*)((char*)sVl + off) = lo;
            }
        }
        __syncthreads();

        // ---- S = Q.K^T  (3 passes: qh.kh, qh.kl, ql.kh)
        float S[8][4];
        #pragma unroll
        for (int nt = 0; nt < 8; nt++)
            #pragma unroll
            for (int k = 0; k < 4; k++) S[nt][k] = 0.f;

        const int brow_h = ((lane >> 4) & 1) * 8 + (lane & 7);   // within n-tile pair
        const int ccb    = (lane >> 3) & 1;
        #pragma unroll
        for (int pass = 0; pass < 3; pass++) {
            const uint32_t kb = (pass == 1) ? bKl : bKh;
            uint32_t (*af)[4] = (pass == 2) ? qlf : qhf;
            #pragma unroll
            for (int ks = 0; ks < 4; ks++) {
                #pragma unroll
                for (int tp = 0; tp < 4; tp++) {
                    const int brow = tp * 16 + brow_h;
                    const uint32_t addr = kb + (uint32_t)brow * 128u +
                        (uint32_t)((((ks * 2 + ccb)) ^ (brow & 7)) << 4);
                    uint32_t r0, r1, r2, r3;
                    LDSM_X4(r0, r1, r2, r3, addr);
                    uint32_t b0[2] = { r0, r1 };
                    uint32_t b1[2] = { r2, r3 };
                    MMA16816(S[2 * tp],     af[ks], b0);
                    MMA16816(S[2 * tp + 1], af[ks], b1);
                }
            }
        }

        // ---- masked online softmax on fragments
        const bool diag = (kt == qt);
        const int r0l = wq * 16 + g;
        const int r1l = r0l + 8;
        float pv[8][4];
        float mx0 = -1e30f, mx1 = -1e30f;
        #pragma unroll
        for (int t = 0; t < 8; t++) {
            const int c0 = t * 8 + qq * 2;
            float s0 = S[t][0] * 0.125f;
            float s1 = S[t][1] * 0.125f;
            float s2 = S[t][2] * 0.125f;
            float s3 = S[t][3] * 0.125f;
            if (diag) {
                if (c0     > r0l) s0 = -1e30f;
                if (c0 + 1 > r0l) s1 = -1e30f;
                if (c0     > r1l) s2 = -1e30f;
                if (c0 + 1 > r1l) s3 = -1e30f;
            }
            pv[t][0] = s0; pv[t][1] = s1; pv[t][2] = s2; pv[t][3] = s3;
            mx0 = fmaxf(mx0, fmaxf(s0, s1));
            mx1 = fmaxf(mx1, fmaxf(s2, s3));
        }
        mx0 = fmaxf(mx0, __shfl_xor_sync(0xffffffffu, mx0, 1));
        mx0 = fmaxf(mx0, __shfl_xor_sync(0xffffffffu, mx0, 2));
        mx1 = fmaxf(mx1, __shfl_xor_sync(0xffffffffu, mx1, 1));
        mx1 = fmaxf(mx1, __shfl_xor_sync(0xffffffffu, mx1, 2));
        const float mn0 = fmaxf(m0, mx0);
        const float mn1 = fmaxf(m1, mx1);
        const float al0 = __expf(m0 - mn0);
        const float al1 = __expf(m1 - mn1);
        m0 = mn0; m1 = mn1;
        float sum0 = 0.f, sum1 = 0.f;
        #pragma unroll
        for (int t = 0; t < 8; t++) {
            const float p0 = __expf(pv[t][0] - mn0);
            const float p1 = __expf(pv[t][1] - mn0);
            const float p2 = __expf(pv[t][2] - mn1);
            const float p3 = __expf(pv[t][3] - mn1);
            pv[t][0] = p0; pv[t][1] = p1; pv[t][2] = p2; pv[t][3] = p3;
            sum0 += p0 + p1;
            sum1 += p2 + p3;
        }
        sum0 += __shfl_xor_sync(0xffffffffu, sum0, 1);
        sum0 += __shfl_xor_sync(0xffffffffu, sum0, 2);
        sum1 += __shfl_xor_sync(0xffffffffu, sum1, 1);
        sum1 += __shfl_xor_sync(0xffffffffu, sum1, 2);
        l0 = l0 * al0 + sum0;
        l1 = l1 * al1 + sum1;

        // ---- P fragments (acc layout == A-operand layout; hi/lo split)
        uint32_t pha[4][4], pla[4][4];
        #pragma unroll
        for (int s = 0; s < 4; s++) {
            bsplit2(pv[2 * s][0],     pv[2 * s][1],     pha[s][0], pla[s][0]);
            bsplit2(pv[2 * s][2],     pv[2 * s][3],     pha[s][1], pla[s][1]);
            bsplit2(pv[2 * s + 1][0], pv[2 * s + 1][1], pha[s][2], pla[s][2]);
            bsplit2(pv[2 * s + 1][2], pv[2 * s + 1][3], pha[s][3], pla[s][3]);
        }

        // ---- rescale O by alpha
        #pragma unroll
        for (int dt = 0; dt < 8; dt++) {
            O[dt][0] *= al0; O[dt][1] *= al0;
            O[dt][2] *= al1; O[dt][3] *= al1;
        }

        // ---- O += P.V  (passes: ph.vh, pl.vh, ph.vl)
        const int jrow_h = ((lane >> 3) & 1) * 8 + (lane & 7);
        const int dccb   = (lane >> 4) & 1;
        #pragma unroll
        for (int s = 0; s < 4; s++) {
            const int jrow = s * 16 + jrow_h;
            const uint32_t rbase = (uint32_t)jrow * 128u;
            const int rm = jrow & 7;
            uint32_t bv[8][2];
            #pragma unroll
            for (int tp = 0; tp < 4; tp++) {
                const uint32_t addr = bVh + rbase +
                    (uint32_t)(((tp * 2 + dccb) ^ rm) << 4);
                uint32_t r0, r1, r2, r3;
                LDSM_X4T(r0, r1, r2, r3, addr);
                bv[2 * tp][0] = r0;     bv[2 * tp][1] = r1;
                bv[2 * tp + 1][0] = r2; bv[2 * tp + 1][1] = r3;
            }
            #pragma unroll
            for (int dt = 0; dt < 8; dt++) {
                MMA16816(O[dt], pha[s], bv[dt]);
                MMA16816(O[dt], pla[s], bv[dt]);
            }
            #pragma unroll
            for (int tp = 0; tp < 4; tp++) {
                const uint32_t addr = bVl + rbase +
                    (uint32_t)(((tp * 2 + dccb) ^ rm) << 4);
                uint32_t r0, r1, r2, r3;
                LDSM_X4T(r0, r1, r2, r3, addr);
                bv[2 * tp][0] = r0;     bv[2 * tp][1] = r1;
                bv[2 * tp + 1][0] = r2; bv[2 * tp + 1][1] = r3;
            }
            #pragma unroll
            for (int dt = 0; dt < 8; dt++)
                MMA16816(O[dt], pha[s], bv[dt]);
        }
    }

    // ---- epilogue: O /= l, split-pack bf16 -> a3 [ah|ah|al]
    const float inv0 = 1.0f / l0;
    const float inv1 = 1.0f / l1;
    const size_t tok0 = (size_t)(b * C_S + qt * 64 + wq * 16 + g);
    const size_t tok1 = tok0 + 8;
    #pragma unroll
    for (int t = 0; t < 8; t++) {
        const int col = h * 64 + t * 8 + qq * 2;
        uint32_t hi, lo;
        bsplit2(O[t][0] * inv0, O[t][1] * inv0, hi, lo);
        __nv_bfloat16* p0 = a3 + tok0 * K3 + col;
        *(uint32_t*)(p0)          = hi;
        *(uint32_t*)(p0 + C_E)    = hi;
        *(uint32_t*)(p0 + 2*C_E)  = lo;
        bsplit2(O[t][2] * inv1, O[t][3] * inv1, hi, lo);
        __nv_bfloat16* p1 = a3 + tok1 * K3 + col;
        *(uint32_t*)(p1)          = hi;
        *(uint32_t*)(p1 + C_E)    = hi;
        *(uint32_t*)(p1 + 2*C_E)  = lo;
    }
}

// ---------------------------------------------------------------------------
extern "C" void kernel_launch(void* const* d_in, const int* in_sizes, int n_in,
                              void* d_out, int out_size)
{
    (void)in_sizes; (void)n_in; (void)out_size;
    const float* x  = (const float*)d_in[0];
    const float* Wa = (const float*)d_in[1];
    const float* ba = (const float*)d_in[2];
    const float* Wp = (const float*)d_in[3];
    const float* bp = (const float*)d_in[4];
    float* out = (float*)d_out;

    float* qkv; __nv_bfloat16 *x3, *a3, *wa3, *wp3;
    cudaGetSymbolAddress((void**)&qkv, g_qkv);
    cudaGetSymbolAddress((void**)&x3,  g_x3);
    cudaGetSymbolAddress((void**)&a3,  g_a3);
    cudaGetSymbolAddress((void**)&wa3, g_wa3);
    cudaGetSymbolAddress((void**)&wp3, g_wp3);

    cudaFuncSetAttribute(hgemm_bf16_kernel,
                         cudaFuncAttributeMaxDynamicSharedMemorySize, 65536);

    // Stage 0: packing
    split_pack_kernel<<<(C_TOK * C_E / 4) / 256, 256>>>(x, x3);
    transpose_pack_kernel<<<dim3(C_3E / 32, C_E / 32), dim3(32, 8)>>>(Wa, wa3, C_3E);
    transpose_pack_kernel<<<dim3(C_E  / 32, C_E / 32), dim3(32, 8)>>>(Wp, wp3, C_E);

    // Stage 1: QKV projection
    hgemm_bf16_kernel<<<dim3(C_3E / 128, C_TOK / 128), 128, 65536>>>(x3, wa3, ba, qkv, C_3E);

    // Stage 2: causal flash attention (tensor cores) -> packed A3
    flash_mma_kernel<<<dim3(C_S / 64, 4 * C_H), 128>>>(qkv, a3);

    // Stage 3: output projection
    hgemm_bf16_kernel<<<dim3(C_E / 128, C_TOK / 128), 128, 65536>>>(a3, wp3, bp, out, C_E);
}

// round 13
// speedup vs baseline: 1.3145x; 1.3145x over previous
#include <cuda_runtime.h>
#include <cuda_bf16.h>
#include <cstdint>

// ---------------------------------------------------------------------------
// MultiHeadAttention (B=4, S=2048, E=1024, H=16, hd=64), fp32 in/out.
// All heavy math on legacy tensor path (mma.sync.m16n8k16 bf16) with 3-term
// hi/lo splits for fp32-level accuracy:
//   GEMMs: A3=[ah|ah|al], B3=[bh|bl|bh] packed along K (K'=3072)
//   Flash: S = qh.kh + qh.kl + ql.kh ; O += ph.vh + ph.vl + pl.vh
// R12: hgemm = R6 shape (8 warps x 64x32) but KC=64, 3-stage pipeline
//      (half the barriers, 64-MMA bursts per warp per chunk).
// ---------------------------------------------------------------------------

#define C_S   2048
#define C_E   1024
#define C_3E  3072
#define C_H   16
#define C_TOK 8192
#define K3    3072
#define KC    64
#define NCH   (K3/KC)   // 48
#define NSTAGE 3
#define STG_BYTES 16384u   // 128 rows x 128 B per operand per stage

// ---------------- common helpers ----------------
__device__ __forceinline__ uint32_t smem_u32(const void* p) {
    uint32_t a;
    asm("{ .reg .u64 t; cvta.to.shared.u64 t, %1; cvt.u32.u64 %0, t; }" : "=r"(a) : "l"(p));
    return a;
}
__device__ __forceinline__ void cpa16(uint32_t s, const void* g) {
    asm volatile("cp.async.cg.shared.global [%0], [%1], 16;" :: "r"(s), "l"(g));
}
#define CP_COMMIT() asm volatile("cp.async.commit_group;" ::: "memory")
#define CP_WAIT(n)  asm volatile("cp.async.wait_group %0;" :: "n"(n) : "memory")
#define LDSM_X4(r0,r1,r2,r3,addr) \
    asm volatile("ldmatrix.sync.aligned.m8n8.x4.shared.b16 {%0,%1,%2,%3}, [%4];" \
                 : "=r"(r0),"=r"(r1),"=r"(r2),"=r"(r3) : "r"(addr))
#define LDSM_X4T(r0,r1,r2,r3,addr) \
    asm volatile("ldmatrix.sync.aligned.m8n8.x4.trans.shared.b16 {%0,%1,%2,%3}, [%4];" \
                 : "=r"(r0),"=r"(r1),"=r"(r2),"=r"(r3) : "r"(addr))
#define MMA16816(d, a, b) \
    asm volatile("mma.sync.aligned.m16n8k16.row.col.f32.bf16.bf16.f32 " \
                 "{%0,%1,%2,%3},{%4,%5,%6,%7},{%8,%9},{%0,%1,%2,%3};" \
                 : "+f"((d)[0]),"+f"((d)[1]),"+f"((d)[2]),"+f"((d)[3]) \
                 : "r"((a)[0]),"r"((a)[1]),"r"((a)[2]),"r"((a)[3]), \
                   "r"((b)[0]),"r"((b)[1]))

__device__ __forceinline__ uint32_t pkbf2(float a, float b) {
    __nv_bfloat162 h = __floats2bfloat162_rn(a, b);
    return *reinterpret_cast<uint32_t*>(&h);
}
__device__ __forceinline__ void bsplit2(float a, float b, uint32_t& hi, uint32_t& lo) {
    const __nv_bfloat16 ah = __float2bfloat16_rn(a);
    const __nv_bfloat16 bh = __float2bfloat16_rn(b);
    __nv_bfloat162 hp; hp.x = ah; hp.y = bh;
    hi = *reinterpret_cast<uint32_t*>(&hp);
    lo = pkbf2(a - __bfloat162float(ah), b - __bfloat162float(bh));
}

// ---------------- device-global scratch ----------------
__device__ float          g_qkv[(size_t)C_TOK * C_3E];
__device__ __nv_bfloat16  g_x3[(size_t)C_TOK * K3];
__device__ __nv_bfloat16  g_a3[(size_t)C_TOK * K3];
__device__ __nv_bfloat16  g_wa3[(size_t)C_3E * K3];
__device__ __nv_bfloat16  g_wp3[(size_t)C_E * K3];

// ---------------------------------------------------------------------------
// split-pack x: fp32 [M][1024] -> bf16 [M][3072] = [ah | ah | al]
// ---------------------------------------------------------------------------
__global__ __launch_bounds__(256)
void split_pack_kernel(const float* __restrict__ in, __nv_bfloat16* __restrict__ o3)
{
    const int i4 = blockIdx.x * 256 + threadIdx.x;
    const int m  = i4 >> 8;
    const int kq = i4 & 255;
    const float4 v = *(const float4*)(in + (size_t)m * C_E + kq * 4);
    uint32_t h0, l0, h1, l1;
    bsplit2(v.x, v.y, h0, l0);
    bsplit2(v.z, v.w, h1, l1);
    uint2 hh = make_uint2(h0, h1);
    uint2 ll = make_uint2(l0, l1);
    __nv_bfloat16* base = o3 + (size_t)m * K3 + kq * 4;
    *(uint2*)(base)          = hh;
    *(uint2*)(base + C_E)    = hh;
    *(uint2*)(base + 2*C_E)  = ll;
}

// ---------------------------------------------------------------------------
// transpose + split-pack W[K=1024][N] -> Wt3[N][3072] = [bh | bl | bh]
// ---------------------------------------------------------------------------
__global__ __launch_bounds__(256)
void transpose_pack_kernel(const float* __restrict__ W, __nv_bfloat16* __restrict__ T3, int N)
{
    __shared__ float t[32][33];
    const int tx = threadIdx.x, ty = threadIdx.y;
    const int n0 = blockIdx.x * 32, k0 = blockIdx.y * 32;
    #pragma unroll
    for (int i = 0; i < 4; i++)
        t[ty + i * 8][tx] = W[(size_t)(k0 + ty + i * 8) * N + n0 + tx];
    __syncthreads();
    #pragma unroll
    for (int i = 0; i < 4; i++) {
        const float v = t[tx][ty + i * 8];
        const __nv_bfloat16 bh = __float2bfloat16_rn(v);
        const __nv_bfloat16 bl = __float2bfloat16_rn(v - __bfloat162float(bh));
        __nv_bfloat16* base = T3 + (size_t)(n0 + ty + i * 8) * K3 + k0 + tx;
        base[0]       = bh;
        base[C_E]     = bl;
        base[2*C_E]   = bh;
    }
}

// ---------------------------------------------------------------------------
// bf16 HGEMM: C = A3 @ B3^T + bias. CTA 128x128, 8 warps x (64x32) warp tiles,
// K-chunk 64, 3-stage cp.async pipeline, ONE __syncthreads per chunk.
// smem row = 128B (8x16B chunks), chunk cc stored at cc^(r&7).
// ---------------------------------------------------------------------------
__global__ __launch_bounds__(256, 2)
void hgemm_bf16_kernel(const __nv_bfloat16* __restrict__ A3,
                       const __nv_bfloat16* __restrict__ B3,
                       const float* __restrict__ bias,
                       float* __restrict__ C, int N)
{
    extern __shared__ __align__(16) unsigned char dsm[];
    // A stages: [0, 48KB), B stages: [48KB, 96KB); 16KB per stage each
    __shared__ float bias_s[128];

    const int t    = threadIdx.x;
    const int lane = t & 31;
    const int wid  = t >> 5;
    const int bm   = blockIdx.y * 128;
    const int bn   = blockIdx.x * 128;
    const int wm   = (wid & 1) * 64;
    const int wn   = (wid >> 1) * 32;

    if (t < 128) bias_s[t] = bias[bn + t];

    const uint32_t sa = smem_u32(dsm);
    const uint32_t sb = sa + NSTAGE * STG_BYTES;

    // ---- fill mapping: thread -> 4 adjacent 16B chunks (half a 128B row)
    const int fr   = t >> 1;              // row 0..127
    const int half = t & 1;               // chunks 0..3 or 4..7
    uint32_t so[4];
    #pragma unroll
    for (int j = 0; j < 4; j++)
        so[j] = (uint32_t)fr * 128u + (uint32_t)(((half * 4 + j) ^ (fr & 7)) << 4);
    const __nv_bfloat16* gA = A3 + (size_t)(bm + fr) * K3 + half * 32;
    const __nv_bfloat16* gB = B3 + (size_t)(bn + fr) * K3 + half * 32;

    // ---- ldmatrix per-lane address precompute
    const int lr = lane & 7;
    const int ccA = (lane >> 4) & 1;      // k 16B-chunk bit for A tiles
    const int ahalf = (lane >> 3) & 1;    // m 8-row half
    const int ccB = (lane >> 3) & 1;      // k 16B-chunk bit for B tiles
    const int bhalf = (lane >> 4) & 1;    // n 8-row half
    uint32_t offA[4]; int rm7A[4];
    #pragma unroll
    for (int i = 0; i < 4; i++) {
        const int r = wm + i * 16 + ahalf * 8 + lr;
        offA[i] = (uint32_t)r * 128u; rm7A[i] = r & 7;
    }
    uint32_t offB[2]; int rm7B[2];
    #pragma unroll
    for (int j = 0; j < 2; j++) {
        const int r = wn + j * 16 + bhalf * 8 + lr;
        offB[j] = (uint32_t)r * 128u; rm7B[j] = r & 7;
    }

    float acc[4][4][4];
    #pragma unroll
    for (int i = 0; i < 4; i++)
        #pragma unroll
        for (int n = 0; n < 4; n++)
            #pragma unroll
            for (int k = 0; k < 4; k++) acc[i][n][k] = 0.f;

    // prologue: stages 0..1
    #pragma unroll
    for (int p = 0; p < NSTAGE - 1; p++) {
        const uint32_t d = (uint32_t)p * STG_BYTES;
        #pragma unroll
        for (int j = 0; j < 4; j++) {
            cpa16(sa + d + so[j], gA + p * KC + j * 8);
            cpa16(sb + d + so[j], gB + p * KC + j * 8);
        }
        CP_COMMIT();
    }

    int stage = 0;
    for (int c = 0; c < NCH; c++) {
        CP_WAIT(NSTAGE - 2);
        __syncthreads();
        if (c + NSTAGE - 1 < NCH) {
            int ps = stage + (NSTAGE - 1); if (ps >= NSTAGE) ps -= NSTAGE;
            const uint32_t d = (uint32_t)ps * STG_BYTES;
            #pragma unroll
            for (int j = 0; j < 4; j++) {
                cpa16(sa + d + so[j], gA + (c + NSTAGE - 1) * KC + j * 8);
                cpa16(sb + d + so[j], gB + (c + NSTAGE - 1) * KC + j * 8);
            }
        }
        CP_COMMIT();   // empty group in tail keeps wait_group accounting exact

        const uint32_t ab = sa + (uint32_t)stage * STG_BYTES;
        const uint32_t bb = sb + (uint32_t)stage * STG_BYTES;
        #pragma unroll
        for (int s = 0; s < 4; s++) {
            uint32_t a[4][4];
            #pragma unroll
            for (int i = 0; i < 4; i++) {
                const uint32_t addr = ab + offA[i] +
                    (uint32_t)((((s << 1) | ccA) ^ rm7A[i]) << 4);
                LDSM_X4(a[i][0], a[i][1], a[i][2], a[i][3], addr);
            }
            uint32_t bfr[4][2];
            #pragma unroll
            for (int j = 0; j < 2; j++) {
                const uint32_t addr = bb + offB[j] +
                    (uint32_t)((((s << 1) | ccB) ^ rm7B[j]) << 4);
                uint32_t r0, r1, r2, r3;
                LDSM_X4(r0, r1, r2, r3, addr);
                bfr[2 * j][0] = r0;     bfr[2 * j][1] = r1;
                bfr[2 * j + 1][0] = r2; bfr[2 * j + 1][1] = r3;
            }
            #pragma unroll
            for (int i = 0; i < 4; i++)
                #pragma unroll
                for (int n = 0; n < 4; n++)
                    MMA16816(acc[i][n], a[i], bfr[n]);
        }
        if (++stage >= NSTAGE) stage = 0;
    }

    __syncthreads();
    #pragma unroll
    for (int i = 0; i < 4; i++) {
        const int row0 = bm + wm + i * 16 + (lane >> 2);
        #pragma unroll
        for (int n = 0; n < 4; n++) {
            const int lcol = wn + n * 8 + (lane & 3) * 2;
            const int col  = bn + lcol;
            const float b0 = bias_s[lcol], b1 = bias_s[lcol + 1];
            float2 v0 = make_float2(acc[i][n][0] + b0, acc[i][n][1] + b1);
            float2 v1 = make_float2(acc[i][n][2] + b0, acc[i][n][3] + b1);
            *(float2*)(C + (size_t)row0 * N + col)       = v0;
            *(float2*)(C + (size_t)(row0 + 8) * N + col) = v1;
        }
    }
}

// ---------------------------------------------------------------------------
// Flash attention on tensor cores (FA2-style). Block = 128 thr (4 warps),
// each warp owns 16 q-rows of a 64-row q-tile. hi/lo bf16 splits everywhere.
// K is B-operand directly ([j][d] rows); V via ldmatrix.trans; P stays in regs.
// smem rows = 128B (8 chunks), chunk cc stored at cc^(r&7).
// ---------------------------------------------------------------------------
__global__ __launch_bounds__(128, 3)
void flash_mma_kernel(const float* __restrict__ qkv, __nv_bfloat16* __restrict__ a3)
{
    __shared__ __align__(16) __nv_bfloat16 sQh[64 * 64], sQl[64 * 64];
    __shared__ __align__(16) __nv_bfloat16 sKh[64 * 64], sKl[64 * 64];
    __shared__ __align__(16) __nv_bfloat16 sVh[64 * 64], sVl[64 * 64];

    const int qt  = (int)gridDim.x - 1 - (int)blockIdx.x;
    const int bh  = blockIdx.y;
    const int b   = bh >> 4;
    const int h   = bh & 15;
    const int tid = threadIdx.x;
    const int lane = tid & 31;
    const int wq   = tid >> 5;           // warp q-row block: rows wq*16..+15

    const float* Qg = qkv + (size_t)b * C_S * C_3E + h * 64;
    const float* Kg = Qg + C_E;
    const float* Vg = Qg + 2 * C_E;

    const uint32_t bQh = smem_u32(sQh), bQl = smem_u32(sQl);
    const uint32_t bKh = smem_u32(sKh), bKl = smem_u32(sKl);
    const uint32_t bVh = smem_u32(sVh), bVl = smem_u32(sVl);

    // ---- load Q tile, split to hi/lo smem (64 rows x 8 chunks of 16B)
    #pragma unroll
    for (int it = 0; it < 4; it++) {
        const int ch = it * 128 + tid;
        const int r  = ch >> 3;
        const int cc = ch & 7;
        const float* src = Qg + (size_t)(qt * 64 + r) * C_3E + cc * 8;
        const float4 u = *(const float4*)src;
        const float4 w = *(const float4*)(src + 4);
        uint4 hi, lo;
        bsplit2(u.x, u.y, hi.x, lo.x);
        bsplit2(u.z, u.w, hi.y, lo.y);
        bsplit2(w.x, w.y, hi.z, lo.z);
        bsplit2(w.z, w.w, hi.w, lo.w);
        const uint32_t off = r * 128u + (uint32_t)((cc ^ (r & 7)) << 4);
        *(uint4*)((char*)sQh + off) = hi;
        *(uint4*)((char*)sQl + off) = lo;
    }
    __syncthreads();

    // ---- build Q A-fragments in registers (persist whole kernel)
    uint32_t qhf[4][4], qlf[4][4];
    {
        const int arow = wq * 16 + ((lane >> 3) & 1) * 8 + (lane & 7);
        const uint32_t ro = (uint32_t)arow * 128u;
        const int rm = arow & 7;
        const int cca = (lane >> 4) & 1;
        #pragma unroll
        for (int ks = 0; ks < 4; ks++) {
            const uint32_t co = (uint32_t)(((ks * 2 + cca) ^ rm) << 4);
            LDSM_X4(qhf[ks][0], qhf[ks][1], qhf[ks][2], qhf[ks][3], bQh + ro + co);
            LDSM_X4(qlf[ks][0], qlf[ks][1], qlf[ks][2], qlf[ks][3], bQl + ro + co);
        }
    }

    const int g  = lane >> 2;
    const int qq = lane & 3;
    float m0 = -1e30f, m1 = -1e30f, l0 = 0.f, l1 = 0.f;
    float O[8][4];
    #pragma unroll
    for (int dt = 0; dt < 8; dt++)
        #pragma unroll
        for (int k = 0; k < 4; k++) O[dt][k] = 0.f;

    for (int kt = 0; kt <= qt; kt++) {
        __syncthreads();   // prior iteration's ldmatrix reads of K/V done
        // ---- load K and V tiles, split to hi/lo smem
        #pragma unroll
        for (int it = 0; it < 4; it++) {
            const int ch = it * 128 + tid;
            const int r  = ch >> 3;
            const int cc = ch & 7;
            const uint32_t off = r * 128u + (uint32_t)((cc ^ (r & 7)) << 4);
            {
                const float* src = Kg + (size_t)(kt * 64 + r) * C_3E + cc * 8;
                const float4 u = *(const float4*)src;
                const float4 w = *(const float4*)(src + 4);
                uint4 hi, lo;
                bsplit2(u.x, u.y, hi.x, lo.x);
                bsplit2(u.z, u.w, hi.y, lo.y);
                bsplit2(w.x, w.y, hi.z, lo.z);
                bsplit2(w.z, w.w, hi.w, lo.w);
                *(uint4*)((char*)sKh + off) = hi;
                *(uint4*)((char*)sKl + off) = lo;
            }
            {
                const float* src = Vg + (size_t)(kt * 64 + r) * C_3E + cc * 8;
                const float4 u = *(const float4*)src;
                const float4 w = *(const float4*)(src + 4);
                uint4 hi, lo;
                bsplit2(u.x, u.y, hi.x, lo.x);
                bsplit2(u.z, u.w, hi.y, lo.y);
                bsplit2(w.x, w.y, hi.z, lo.z);
                bsplit2(w.z, w.w, hi.w, lo.w);
                *(uint4*)((char*)sVh + off) = hi;
                *(uint4*)((char*)sVl + off) = lo;
            }
        }
        __syncthreads();

        // ---- S = Q.K^T  (3 passes: qh.kh, qh.kl, ql.kh)
        float S[8][4];
        #pragma unroll
        for (int nt = 0; nt < 8; nt++)
            #pragma unroll
            for (int k = 0; k < 4; k++) S[nt][k] = 0.f;

        const int brow_h = ((lane >> 4) & 1) * 8 + (lane & 7);   // within n-tile pair
        const int ccb    = (lane >> 3) & 1;
        #pragma unroll
        for (int pass = 0; pass < 3; pass++) {
            const uint32_t kb = (pass == 1) ? bKl : bKh;
            uint32_t (*af)[4] = (pass == 2) ? qlf : qhf;
            #pragma unroll
            for (int ks = 0; ks < 4; ks++) {
                #pragma unroll
                for (int tp = 0; tp < 4; tp++) {
                    const int brow = tp * 16 + brow_h;
                    const uint32_t addr = kb + (uint32_t)brow * 128u +
                        (uint32_t)((((ks * 2 + ccb)) ^ (brow & 7)) << 4);
                    uint32_t r0, r1, r2, r3;
                    LDSM_X4(r0, r1, r2, r3, addr);
                    uint32_t b0[2] = { r0, r1 };
                    uint32_t b1[2] = { r2, r3 };
                    MMA16816(S[2 * tp],     af[ks], b0);
                    MMA16816(S[2 * tp + 1], af[ks], b1);
                }
            }
        }

        // ---- masked online softmax on fragments
        const bool diag = (kt == qt);
        const int r0l = wq * 16 + g;
        const int r1l = r0l + 8;
        float pv[8][4];
        float mx0 = -1e30f, mx1 = -1e30f;
        #pragma unroll
        for (int t = 0; t < 8; t++) {
            const int c0 = t * 8 + qq * 2;
            float s0 = S[t][0] * 0.125f;
            float s1 = S[t][1] * 0.125f;
            float s2 = S[t][2] * 0.125f;
            float s3 = S[t][3] * 0.125f;
            if (diag) {
                if (c0     > r0l) s0 = -1e30f;
                if (c0 + 1 > r0l) s1 = -1e30f;
                if (c0     > r1l) s2 = -1e30f;
                if (c0 + 1 > r1l) s3 = -1e30f;
            }
            pv[t][0] = s0; pv[t][1] = s1; pv[t][2] = s2; pv[t][3] = s3;
            mx0 = fmaxf(mx0, fmaxf(s0, s1));
            mx1 = fmaxf(mx1, fmaxf(s2, s3));
        }
        mx0 = fmaxf(mx0, __shfl_xor_sync(0xffffffffu, mx0, 1));
        mx0 = fmaxf(mx0, __shfl_xor_sync(0xffffffffu, mx0, 2));
        mx1 = fmaxf(mx1, __shfl_xor_sync(0xffffffffu, mx1, 1));
        mx1 = fmaxf(mx1, __shfl_xor_sync(0xffffffffu, mx1, 2));
        const float mn0 = fmaxf(m0, mx0);
        const float mn1 = fmaxf(m1, mx1);
        const float al0 = __expf(m0 - mn0);
        const float al1 = __expf(m1 - mn1);
        m0 = mn0; m1 = mn1;
        float sum0 = 0.f, sum1 = 0.f;
        #pragma unroll
        for (int t = 0; t < 8; t++) {
            const float p0 = __expf(pv[t][0] - mn0);
            const float p1 = __expf(pv[t][1] - mn0);
            const float p2 = __expf(pv[t][2] - mn1);
            const float p3 = __expf(pv[t][3] - mn1);
            pv[t][0] = p0; pv[t][1] = p1; pv[t][2] = p2; pv[t][3] = p3;
            sum0 += p0 + p1;
            sum1 += p2 + p3;
        }
        sum0 += __shfl_xor_sync(0xffffffffu, sum0, 1);
        sum0 += __shfl_xor_sync(0xffffffffu, sum0, 2);
        sum1 += __shfl_xor_sync(0xffffffffu, sum1, 1);
        sum1 += __shfl_xor_sync(0xffffffffu, sum1, 2);
        l0 = l0 * al0 + sum0;
        l1 = l1 * al1 + sum1;

        // ---- P fragments (acc layout == A-operand layout; hi/lo split)
        uint32_t pha[4][4], pla[4][4];
        #pragma unroll
        for (int s = 0; s < 4; s++) {
            bsplit2(pv[2 * s][0],     pv[2 * s][1],     pha[s][0], pla[s][0]);
            bsplit2(pv[2 * s][2],     pv[2 * s][3],     pha[s][1], pla[s][1]);
            bsplit2(pv[2 * s + 1][0], pv[2 * s + 1][1], pha[s][2], pla[s][2]);
            bsplit2(pv[2 * s + 1][2], pv[2 * s + 1][3], pha[s][3], pla[s][3]);
        }

        // ---- rescale O by alpha
        #pragma unroll
        for (int dt = 0; dt < 8; dt++) {
            O[dt][0] *= al0; O[dt][1] *= al0;
            O[dt][2] *= al1; O[dt][3] *= al1;
        }

        // ---- O += P.V  (passes: ph.vh, pl.vh, ph.vl)
        const int jrow_h = ((lane >> 3) & 1) * 8 + (lane & 7);
        const int dccb   = (lane >> 4) & 1;
        #pragma unroll
        for (int s = 0; s < 4; s++) {
            const int jrow = s * 16 + jrow_h;
            const uint32_t rbase = (uint32_t)jrow * 128u;
            const int rm = jrow & 7;
            uint32_t bv[8][2];
            #pragma unroll
            for (int tp = 0; tp < 4; tp++) {
                const uint32_t addr = bVh + rbase +
                    (uint32_t)(((tp * 2 + dccb) ^ rm) << 4);
                uint32_t r0, r1, r2, r3;
                LDSM_X4T(r0, r1, r2, r3, addr);
                bv[2 * tp][0] = r0;     bv[2 * tp][1] = r1;
                bv[2 * tp + 1][0] = r2; bv[2 * tp + 1][1] = r3;
            }
            #pragma unroll
            for (int dt = 0; dt < 8; dt++) {
                MMA16816(O[dt], pha[s], bv[dt]);
                MMA16816(O[dt], pla[s], bv[dt]);
            }
            #pragma unroll
            for (int tp = 0; tp < 4; tp++) {
                const uint32_t addr = bVl + rbase +
                    (uint32_t)(((tp * 2 + dccb) ^ rm) << 4);
                uint32_t r0, r1, r2, r3;
                LDSM_X4T(r0, r1, r2, r3, addr);
                bv[2 * tp][0] = r0;     bv[2 * tp][1] = r1;
                bv[2 * tp + 1][0] = r2; bv[2 * tp + 1][1] = r3;
            }
            #pragma unroll
            for (int dt = 0; dt < 8; dt++)
                MMA16816(O[dt], pha[s], bv[dt]);
        }
    }

    // ---- epilogue: O /= l, split-pack bf16 -> a3 [ah|ah|al]
    const float inv0 = 1.0f / l0;
    const float inv1 = 1.0f / l1;
    const size_t tok0 = (size_t)(b * C_S + qt * 64 + wq * 16 + g);
    const size_t tok1 = tok0 + 8;
    #pragma unroll
    for (int t = 0; t < 8; t++) {
        const int col = h * 64 + t * 8 + qq * 2;
        uint32_t hi, lo;
        bsplit2(O[t][0] * inv0, O[t][1] * inv0, hi, lo);
        __nv_bfloat16* p0 = a3 + tok0 * K3 + col;
        *(uint32_t*)(p0)          = hi;
        *(uint32_t*)(p0 + C_E)    = hi;
        *(uint32_t*)(p0 + 2*C_E)  = lo;
        bsplit2(O[t][2] * inv1, O[t][3] * inv1, hi, lo);
        __nv_bfloat16* p1 = a3 + tok1 * K3 + col;
        *(uint32_t*)(p1)          = hi;
        *(uint32_t*)(p1 + C_E)    = hi;
        *(uint32_t*)(p1 + 2*C_E)  = lo;
    }
}

// ---------------------------------------------------------------------------
extern "C" void kernel_launch(void* const* d_in, const int* in_sizes, int n_in,
                              void* d_out, int out_size)
{
    (void)in_sizes; (void)n_in; (void)out_size;
    const float* x  = (const float*)d_in[0];
    const float* Wa = (const float*)d_in[1];
    const float* ba = (const float*)d_in[2];
    const float* Wp = (const float*)d_in[3];
    const float* bp = (const float*)d_in[4];
    float* out = (float*)d_out;

    float* qkv; __nv_bfloat16 *x3, *a3, *wa3, *wp3;
    cudaGetSymbolAddress((void**)&qkv, g_qkv);
    cudaGetSymbolAddress((void**)&x3,  g_x3);
    cudaGetSymbolAddress((void**)&a3,  g_a3);
    cudaGetSymbolAddress((void**)&wa3, g_wa3);
    cudaGetSymbolAddress((void**)&wp3, g_wp3);

    const int smem_bytes = 2 * NSTAGE * (int)STG_BYTES;   // 96 KB
    cudaFuncSetAttribute(hgemm_bf16_kernel,
                         cudaFuncAttributeMaxDynamicSharedMemorySize, smem_bytes);

    // Stage 0: packing
    split_pack_kernel<<<(C_TOK * C_E / 4) / 256, 256>>>(x, x3);
    transpose_pack_kernel<<<dim3(C_3E / 32, C_E / 32), dim3(32, 8)>>>(Wa, wa3, C_3E);
    transpose_pack_kernel<<<dim3(C_E  / 32, C_E / 32), dim3(32, 8)>>>(Wp, wp3, C_E);

    // Stage 1: QKV projection
    hgemm_bf16_kernel<<<dim3(C_3E / 128, C_TOK / 128), 256, smem_bytes>>>(x3, wa3, ba, qkv, C_3E);

    // Stage 2: causal flash attention (tensor cores) -> packed A3
    flash_mma_kernel<<<dim3(C_S / 64, 4 * C_H), 128>>>(qkv, a3);

    // Stage 3: output projection
    hgemm_bf16_kernel<<<dim3(C_E / 128, C_TOK / 128), 256, smem_bytes>>>(a3, wp3, bp, out, C_E);
}

// round 14
// speedup vs baseline: 1.3398x; 1.0193x over previous
#include <cuda_runtime.h>
#include <cuda_bf16.h>
#include <cstdint>

// ---------------------------------------------------------------------------
// MultiHeadAttention (B=4, S=2048, E=1024, H=16, hd=64), fp32 in/out.
// All heavy math on legacy tensor path (mma.sync.m16n8k16 bf16) with 3-term
// hi/lo splits for fp32-level accuracy:
//   GEMMs: A3=[ah|ah|al], B3=[bh|bl|bh] packed along K (K'=3072)
//   Flash: S = qh.kh + qh.kl + ql.kh ; O += ph.vh + ph.vl + pl.vh
// R12: hgemm 8 warps x 64x32, KC=64, 3-stage pipeline.
// R14: stage-1 hgemm writes QKV pre-split to bf16 hi/lo planes; flash inner
//      loop does plain bf16 tile copies (no conversions, half the bytes).
// ---------------------------------------------------------------------------

#define C_S   2048
#define C_E   1024
#define C_3E  3072
#define C_H   16
#define C_TOK 8192
#define K3    3072
#define KC    64
#define NCH   (K3/KC)   // 48
#define NSTAGE 3
#define STG_BYTES 16384u   // 128 rows x 128 B per operand per stage

// ---------------- common helpers ----------------
__device__ __forceinline__ uint32_t smem_u32(const void* p) {
    uint32_t a;
    asm("{ .reg .u64 t; cvta.to.shared.u64 t, %1; cvt.u32.u64 %0, t; }" : "=r"(a) : "l"(p));
    return a;
}
__device__ __forceinline__ void cpa16(uint32_t s, const void* g) {
    asm volatile("cp.async.cg.shared.global [%0], [%1], 16;" :: "r"(s), "l"(g));
}
#define CP_COMMIT() asm volatile("cp.async.commit_group;" ::: "memory")
#define CP_WAIT(n)  asm volatile("cp.async.wait_group %0;" :: "n"(n) : "memory")
#define LDSM_X4(r0,r1,r2,r3,addr) \
    asm volatile("ldmatrix.sync.aligned.m8n8.x4.shared.b16 {%0,%1,%2,%3}, [%4];" \
                 : "=r"(r0),"=r"(r1),"=r"(r2),"=r"(r3) : "r"(addr))
#define LDSM_X4T(r0,r1,r2,r3,addr) \
    asm volatile("ldmatrix.sync.aligned.m8n8.x4.trans.shared.b16 {%0,%1,%2,%3}, [%4];" \
                 : "=r"(r0),"=r"(r1),"=r"(r2),"=r"(r3) : "r"(addr))
#define MMA16816(d, a, b) \
    asm volatile("mma.sync.aligned.m16n8k16.row.col.f32.bf16.bf16.f32 " \
                 "{%0,%1,%2,%3},{%4,%5,%6,%7},{%8,%9},{%0,%1,%2,%3};" \
                 : "+f"((d)[0]),"+f"((d)[1]),"+f"((d)[2]),"+f"((d)[3]) \
                 : "r"((a)[0]),"r"((a)[1]),"r"((a)[2]),"r"((a)[3]), \
                   "r"((b)[0]),"r"((b)[1]))

__device__ __forceinline__ uint32_t pkbf2(float a, float b) {
    __nv_bfloat162 h = __floats2bfloat162_rn(a, b);
    return *reinterpret_cast<uint32_t*>(&h);
}
__device__ __forceinline__ void bsplit2(float a, float b, uint32_t& hi, uint32_t& lo) {
    const __nv_bfloat16 ah = __float2bfloat16_rn(a);
    const __nv_bfloat16 bh = __float2bfloat16_rn(b);
    __nv_bfloat162 hp; hp.x = ah; hp.y = bh;
    hi = *reinterpret_cast<uint32_t*>(&hp);
    lo = pkbf2(a - __bfloat162float(ah), b - __bfloat162float(bh));
}

// ---------------- device-global scratch ----------------
__device__ __nv_bfloat16  g_qh3[(size_t)C_TOK * C_3E];   // QKV hi plane (bf16)
__device__ __nv_bfloat16  g_ql3[(size_t)C_TOK * C_3E];   // QKV lo plane (bf16)
__device__ __nv_bfloat16  g_x3[(size_t)C_TOK * K3];      // x packed   [ah|ah|al]
__device__ __nv_bfloat16  g_a3[(size_t)C_TOK * K3];      // attn out packed
__device__ __nv_bfloat16  g_wa3[(size_t)C_3E * K3];      // W_attn^T packed [bh|bl|bh]
__device__ __nv_bfloat16  g_wp3[(size_t)C_E * K3];       // W_proj^T packed

// ---------------------------------------------------------------------------
// split-pack x: fp32 [M][1024] -> bf16 [M][3072] = [ah | ah | al]
// ---------------------------------------------------------------------------
__global__ __launch_bounds__(256)
void split_pack_kernel(const float* __restrict__ in, __nv_bfloat16* __restrict__ o3)
{
    const int i4 = blockIdx.x * 256 + threadIdx.x;
    const int m  = i4 >> 8;
    const int kq = i4 & 255;
    const float4 v = *(const float4*)(in + (size_t)m * C_E + kq * 4);
    uint32_t h0, l0, h1, l1;
    bsplit2(v.x, v.y, h0, l0);
    bsplit2(v.z, v.w, h1, l1);
    uint2 hh = make_uint2(h0, h1);
    uint2 ll = make_uint2(l0, l1);
    __nv_bfloat16* base = o3 + (size_t)m * K3 + kq * 4;
    *(uint2*)(base)          = hh;
    *(uint2*)(base + C_E)    = hh;
    *(uint2*)(base + 2*C_E)  = ll;
}

// ---------------------------------------------------------------------------
// transpose + split-pack W[K=1024][N] -> Wt3[N][3072] = [bh | bl | bh]
// ---------------------------------------------------------------------------
__global__ __launch_bounds__(256)
void transpose_pack_kernel(const float* __restrict__ W, __nv_bfloat16* __restrict__ T3, int N)
{
    __shared__ float t[32][33];
    const int tx = threadIdx.x, ty = threadIdx.y;
    const int n0 = blockIdx.x * 32, k0 = blockIdx.y * 32;
    #pragma unroll
    for (int i = 0; i < 4; i++)
        t[ty + i * 8][tx] = W[(size_t)(k0 + ty + i * 8) * N + n0 + tx];
    __syncthreads();
    #pragma unroll
    for (int i = 0; i < 4; i++) {
        const float v = t[tx][ty + i * 8];
        const __nv_bfloat16 bh = __float2bfloat16_rn(v);
        const __nv_bfloat16 bl = __float2bfloat16_rn(v - __bfloat162float(bh));
        __nv_bfloat16* base = T3 + (size_t)(n0 + ty + i * 8) * K3 + k0 + tx;
        base[0]       = bh;
        base[C_E]     = bl;
        base[2*C_E]   = bh;
    }
}

// ---------------------------------------------------------------------------
// bf16 HGEMM: C = A3 @ B3^T + bias. CTA 128x128, 8 warps x (64x32) warp tiles,
// K-chunk 64, 3-stage cp.async pipeline, ONE __syncthreads per chunk.
// smem row = 128B (8x16B chunks), chunk cc stored at cc^(r&7).
// OUT_SPLIT=0: fp32 C.  OUT_SPLIT=1: bf16 hi/lo planes (for flash input).
// ---------------------------------------------------------------------------
template <int OUT_SPLIT>
__global__ __launch_bounds__(256, 2)
void hgemm_bf16_kernel(const __nv_bfloat16* __restrict__ A3,
                       const __nv_bfloat16* __restrict__ B3,
                       const float* __restrict__ bias,
                       float* __restrict__ C,
                       __nv_bfloat16* __restrict__ OH,
                       __nv_bfloat16* __restrict__ OL,
                       int N)
{
    extern __shared__ __align__(16) unsigned char dsm[];
    __shared__ float bias_s[128];

    const int t    = threadIdx.x;
    const int lane = t & 31;
    const int wid  = t >> 5;
    const int bm   = blockIdx.y * 128;
    const int bn   = blockIdx.x * 128;
    const int wm   = (wid & 1) * 64;
    const int wn   = (wid >> 1) * 32;

    if (t < 128) bias_s[t] = bias[bn + t];

    const uint32_t sa = smem_u32(dsm);
    const uint32_t sb = sa + NSTAGE * STG_BYTES;

    const int fr   = t >> 1;
    const int half = t & 1;
    uint32_t so[4];
    #pragma unroll
    for (int j = 0; j < 4; j++)
        so[j] = (uint32_t)fr * 128u + (uint32_t)(((half * 4 + j) ^ (fr & 7)) << 4);
    const __nv_bfloat16* gA = A3 + (size_t)(bm + fr) * K3 + half * 32;
    const __nv_bfloat16* gB = B3 + (size_t)(bn + fr) * K3 + half * 32;

    const int lr = lane & 7;
    const int ccA = (lane >> 4) & 1;
    const int ahalf = (lane >> 3) & 1;
    const int ccB = (lane >> 3) & 1;
    const int bhalf = (lane >> 4) & 1;
    uint32_t offA[4]; int rm7A[4];
    #pragma unroll
    for (int i = 0; i < 4; i++) {
        const int r = wm + i * 16 + ahalf * 8 + lr;
        offA[i] = (uint32_t)r * 128u; rm7A[i] = r & 7;
    }
    uint32_t offB[2]; int rm7B[2];
    #pragma unroll
    for (int j = 0; j < 2; j++) {
        const int r = wn + j * 16 + bhalf * 8 + lr;
        offB[j] = (uint32_t)r * 128u; rm7B[j] = r & 7;
    }

    float acc[4][4][4];
    #pragma unroll
    for (int i = 0; i < 4; i++)
        #pragma unroll
        for (int n = 0; n < 4; n++)
            #pragma unroll
            for (int k = 0; k < 4; k++) acc[i][n][k] = 0.f;

    #pragma unroll
    for (int p = 0; p < NSTAGE - 1; p++) {
        const uint32_t d = (uint32_t)p * STG_BYTES;
        #pragma unroll
        for (int j = 0; j < 4; j++) {
            cpa16(sa + d + so[j], gA + p * KC + j * 8);
            cpa16(sb + d + so[j], gB + p * KC + j * 8);
        }
        CP_COMMIT();
    }

    int stage = 0;
    for (int c = 0; c < NCH; c++) {
        CP_WAIT(NSTAGE - 2);
        __syncthreads();
        if (c + NSTAGE - 1 < NCH) {
            int ps = stage + (NSTAGE - 1); if (ps >= NSTAGE) ps -= NSTAGE;
            const uint32_t d = (uint32_t)ps * STG_BYTES;
            #pragma unroll
            for (int j = 0; j < 4; j++) {
                cpa16(sa + d + so[j], gA + (c + NSTAGE - 1) * KC + j * 8);
                cpa16(sb + d + so[j], gB + (c + NSTAGE - 1) * KC + j * 8);
            }
        }
        CP_COMMIT();

        const uint32_t ab = sa + (uint32_t)stage * STG_BYTES;
        const uint32_t bb = sb + (uint32_t)stage * STG_BYTES;
        #pragma unroll
        for (int s = 0; s < 4; s++) {
            uint32_t a[4][4];
            #pragma unroll
            for (int i = 0; i < 4; i++) {
                const uint32_t addr = ab + offA[i] +
                    (uint32_t)((((s << 1) | ccA) ^ rm7A[i]) << 4);
                LDSM_X4(a[i][0], a[i][1], a[i][2], a[i][3], addr);
            }
            uint32_t bfr[4][2];
            #pragma unroll
            for (int j = 0; j < 2; j++) {
                const uint32_t addr = bb + offB[j] +
                    (uint32_t)((((s << 1) | ccB) ^ rm7B[j]) << 4);
                uint32_t r0, r1, r2, r3;
                LDSM_X4(r0, r1, r2, r3, addr);
                bfr[2 * j][0] = r0;     bfr[2 * j][1] = r1;
                bfr[2 * j + 1][0] = r2; bfr[2 * j + 1][1] = r3;
            }
            #pragma unroll
            for (int i = 0; i < 4; i++)
                #pragma unroll
                for (int n = 0; n < 4; n++)
                    MMA16816(acc[i][n], a[i], bfr[n]);
        }
        if (++stage >= NSTAGE) stage = 0;
    }

    __syncthreads();
    #pragma unroll
    for (int i = 0; i < 4; i++) {
        const int row0 = bm + wm + i * 16 + (lane >> 2);
        #pragma unroll
        for (int n = 0; n < 4; n++) {
            const int lcol = wn + n * 8 + (lane & 3) * 2;
            const int col  = bn + lcol;
            const float b0 = bias_s[lcol], b1 = bias_s[lcol + 1];
            if (OUT_SPLIT == 0) {
                float2 v0 = make_float2(acc[i][n][0] + b0, acc[i][n][1] + b1);
                float2 v1 = make_float2(acc[i][n][2] + b0, acc[i][n][3] + b1);
                *(float2*)(C + (size_t)row0 * N + col)       = v0;
                *(float2*)(C + (size_t)(row0 + 8) * N + col) = v1;
            } else {
                uint32_t h, l;
                bsplit2(acc[i][n][0] + b0, acc[i][n][1] + b1, h, l);
                *(uint32_t*)(OH + (size_t)row0 * N + col) = h;
                *(uint32_t*)(OL + (size_t)row0 * N + col) = l;
                bsplit2(acc[i][n][2] + b0, acc[i][n][3] + b1, h, l);
                *(uint32_t*)(OH + (size_t)(row0 + 8) * N + col) = h;
                *(uint32_t*)(OL + (size_t)(row0 + 8) * N + col) = l;
            }
        }
    }
}

// ---------------------------------------------------------------------------
// Flash attention on tensor cores (FA2-style). Block = 128 thr (4 warps),
// each warp owns 16 q-rows of a 64-row q-tile. Q/K/V arrive PRE-SPLIT as
// bf16 hi/lo planes -> inner loop is plain uint4 smem fills (no conversion).
// K is B-operand directly ([j][d] rows); V via ldmatrix.trans; P stays in regs.
// smem rows = 128B (8 chunks), chunk cc stored at cc^(r&7).
// ---------------------------------------------------------------------------
__global__ __launch_bounds__(128, 3)
void flash_mma_kernel(const __nv_bfloat16* __restrict__ qh3,
                      const __nv_bfloat16* __restrict__ ql3,
                      __nv_bfloat16* __restrict__ a3)
{
    __shared__ __align__(16) __nv_bfloat16 sQh[64 * 64], sQl[64 * 64];
    __shared__ __align__(16) __nv_bfloat16 sKh[64 * 64], sKl[64 * 64];
    __shared__ __align__(16) __nv_bfloat16 sVh[64 * 64], sVl[64 * 64];

    const int qt  = (int)gridDim.x - 1 - (int)blockIdx.x;
    const int bh  = blockIdx.y;
    const int b   = bh >> 4;
    const int h   = bh & 15;
    const int tid = threadIdx.x;
    const int lane = tid & 31;
    const int wq   = tid >> 5;

    const size_t rowbase = (size_t)b * C_S * C_3E + h * 64;
    const __nv_bfloat16* Qh = qh3 + rowbase;
    const __nv_bfloat16* Ql = ql3 + rowbase;
    const __nv_bfloat16* Kh = Qh + C_E;
    const __nv_bfloat16* Kl = Ql + C_E;
    const __nv_bfloat16* Vh = Qh + 2 * C_E;
    const __nv_bfloat16* Vl = Ql + 2 * C_E;

    const uint32_t bQh = smem_u32(sQh), bQl = smem_u32(sQl);
    const uint32_t bKh = smem_u32(sKh), bKl = smem_u32(sKl);
    const uint32_t bVh = smem_u32(sVh), bVl = smem_u32(sVl);

    // ---- load Q tile (pre-split): 64 rows x 8 chunks of 16B per plane
    #pragma unroll
    for (int it = 0; it < 4; it++) {
        const int ch = it * 128 + tid;
        const int r  = ch >> 3;
        const int cc = ch & 7;
        const size_t go = (size_t)(qt * 64 + r) * C_3E + cc * 8;
        const uint32_t off = r * 128u + (uint32_t)((cc ^ (r & 7)) << 4);
        *(uint4*)((char*)sQh + off) = *(const uint4*)(Qh + go);
        *(uint4*)((char*)sQl + off) = *(const uint4*)(Ql + go);
    }
    __syncthreads();

    // ---- build Q A-fragments in registers (persist whole kernel)
    uint32_t qhf[4][4], qlf[4][4];
    {
        const int arow = wq * 16 + ((lane >> 3) & 1) * 8 + (lane & 7);
        const uint32_t ro = (uint32_t)arow * 128u;
        const int rm = arow & 7;
        const int cca = (lane >> 4) & 1;
        #pragma unroll
        for (int ks = 0; ks < 4; ks++) {
            const uint32_t co = (uint32_t)(((ks * 2 + cca) ^ rm) << 4);
            LDSM_X4(qhf[ks][0], qhf[ks][1], qhf[ks][2], qhf[ks][3], bQh + ro + co);
            LDSM_X4(qlf[ks][0], qlf[ks][1], qlf[ks][2], qlf[ks][3], bQl + ro + co);
        }
    }

    const int g  = lane >> 2;
    const int qq = lane & 3;
    float m0 = -1e30f, m1 = -1e30f, l0 = 0.f, l1 = 0.f;
    float O[8][4];
    #pragma unroll
    for (int dt = 0; dt < 8; dt++)
        #pragma unroll
        for (int k = 0; k < 4; k++) O[dt][k] = 0.f;

    for (int kt = 0; kt <= qt; kt++) {
        __syncthreads();
        // ---- load K and V tiles (pre-split bf16, plain copies)
        #pragma unroll
        for (int it = 0; it < 4; it++) {
            const int ch = it * 128 + tid;
            const int r  = ch >> 3;
            const int cc = ch & 7;
            const size_t go = (size_t)(kt * 64 + r) * C_3E + cc * 8;
            const uint32_t off = r * 128u + (uint32_t)((cc ^ (r & 7)) << 4);
            *(uint4*)((char*)sKh + off) = *(const uint4*)(Kh + go);
            *(uint4*)((char*)sKl + off) = *(const uint4*)(Kl + go);
            *(uint4*)((char*)sVh + off) = *(const uint4*)(Vh + go);
            *(uint4*)((char*)sVl + off) = *(const uint4*)(Vl + go);
        }
        __syncthreads();

        // ---- S = Q.K^T  (3 passes: qh.kh, qh.kl, ql.kh)
        float S[8][4];
        #pragma unroll
        for (int nt = 0; nt < 8; nt++)
            #pragma unroll
            for (int k = 0; k < 4; k++) S[nt][k] = 0.f;

        const int brow_h = ((lane >> 4) & 1) * 8 + (lane & 7);
        const int ccb    = (lane >> 3) & 1;
        #pragma unroll
        for (int pass = 0; pass < 3; pass++) {
            const uint32_t kb = (pass == 1) ? bKl : bKh;
            uint32_t (*af)[4] = (pass == 2) ? qlf : qhf;
            #pragma unroll
            for (int ks = 0; ks < 4; ks++) {
                #pragma unroll
                for (int tp = 0; tp < 4; tp++) {
                    const int brow = tp * 16 + brow_h;
                    const uint32_t addr = kb + (uint32_t)brow * 128u +
                        (uint32_t)((((ks * 2 + ccb)) ^ (brow & 7)) << 4);
                    uint32_t r0, r1, r2, r3;
                    LDSM_X4(r0, r1, r2, r3, addr);
                    uint32_t b0[2] = { r0, r1 };
                    uint32_t b1[2] = { r2, r3 };
                    MMA16816(S[2 * tp],     af[ks], b0);
                    MMA16816(S[2 * tp + 1], af[ks], b1);
                }
            }
        }

        // ---- masked online softmax on fragments
        const bool diag = (kt == qt);
        const int r0l = wq * 16 + g;
        const int r1l = r0l + 8;
        float pv[8][4];
        float mx0 = -1e30f, mx1 = -1e30f;
        #pragma unroll
        for (int t = 0; t < 8; t++) {
            const int c0 = t * 8 + qq * 2;
            float s0 = S[t][0] * 0.125f;
            float s1 = S[t][1] * 0.125f;
            float s2 = S[t][2] * 0.125f;
            float s3 = S[t][3] * 0.125f;
            if (diag) {
                if (c0     > r0l) s0 = -1e30f;
                if (c0 + 1 > r0l) s1 = -1e30f;
                if (c0     > r1l) s2 = -1e30f;
                if (c0 + 1 > r1l) s3 = -1e30f;
            }
            pv[t][0] = s0; pv[t][1] = s1; pv[t][2] = s2; pv[t][3] = s3;
            mx0 = fmaxf(mx0, fmaxf(s0, s1));
            mx1 = fmaxf(mx1, fmaxf(s2, s3));
        }
        mx0 = fmaxf(mx0, __shfl_xor_sync(0xffffffffu, mx0, 1));
        mx0 = fmaxf(mx0, __shfl_xor_sync(0xffffffffu, mx0, 2));
        mx1 = fmaxf(mx1, __shfl_xor_sync(0xffffffffu, mx1, 1));
        mx1 = fmaxf(mx1, __shfl_xor_sync(0xffffffffu, mx1, 2));
        const float mn0 = fmaxf(m0, mx0);
        const float mn1 = fmaxf(m1, mx1);
        const float al0 = __expf(m0 - mn0);
        const float al1 = __expf(m1 - mn1);
        m0 = mn0; m1 = mn1;
        float sum0 = 0.f, sum1 = 0.f;
        #pragma unroll
        for (int t = 0; t < 8; t++) {
            const float p0 = __expf(pv[t][0] - mn0);
            const float p1 = __expf(pv[t][1] - mn0);
            const float p2 = __expf(pv[t][2] - mn1);
            const float p3 = __expf(pv[t][3] - mn1);
            pv[t][0] = p0; pv[t][1] = p1; pv[t][2] = p2; pv[t][3] = p3;
            sum0 += p0 + p1;
            sum1 += p2 + p3;
        }
        sum0 += __shfl_xor_sync(0xffffffffu, sum0, 1);
        sum0 += __shfl_xor_sync(0xffffffffu, sum0, 2);
        sum1 += __shfl_xor_sync(0xffffffffu, sum1, 1);
        sum1 += __shfl_xor_sync(0xffffffffu, sum1, 2);
        l0 = l0 * al0 + sum0;
        l1 = l1 * al1 + sum1;

        // ---- P fragments (acc layout == A-operand layout; hi/lo split)
        uint32_t pha[4][4], pla[4][4];
        #pragma unroll
        for (int s = 0; s < 4; s++) {
            bsplit2(pv[2 * s][0],     pv[2 * s][1],     pha[s][0], pla[s][0]);
            bsplit2(pv[2 * s][2],     pv[2 * s][3],     pha[s][1], pla[s][1]);
            bsplit2(pv[2 * s + 1][0], pv[2 * s + 1][1], pha[s][2], pla[s][2]);
            bsplit2(pv[2 * s + 1][2], pv[2 * s + 1][3], pha[s][3], pla[s][3]);
        }

        // ---- rescale O by alpha
        #pragma unroll
        for (int dt = 0; dt < 8; dt++) {
            O[dt][0] *= al0; O[dt][1] *= al0;
            O[dt][2] *= al1; O[dt][3] *= al1;
        }

        // ---- O += P.V  (passes: ph.vh, pl.vh, ph.vl)
        const int jrow_h = ((lane >> 3) & 1) * 8 + (lane & 7);
        const int dccb   = (lane >> 4) & 1;
        #pragma unroll
        for (int s = 0; s < 4; s++) {
            const int jrow = s * 16 + jrow_h;
            const uint32_t rbase = (uint32_t)jrow * 128u;
            const int rm = jrow & 7;
            uint32_t bv[8][2];
            #pragma unroll
            for (int tp = 0; tp < 4; tp++) {
                const uint32_t addr = bVh + rbase +
                    (uint32_t)(((tp * 2 + dccb) ^ rm) << 4);
                uint32_t r0, r1, r2, r3;
                LDSM_X4T(r0, r1, r2, r3, addr);
                bv[2 * tp][0] = r0;     bv[2 * tp][1] = r1;
                bv[2 * tp + 1][0] = r2; bv[2 * tp + 1][1] = r3;
            }
            #pragma unroll
            for (int dt = 0; dt < 8; dt++) {
                MMA16816(O[dt], pha[s], bv[dt]);
                MMA16816(O[dt], pla[s], bv[dt]);
            }
            #pragma unroll
            for (int tp = 0; tp < 4; tp++) {
                const uint32_t addr = bVl + rbase +
                    (uint32_t)(((tp * 2 + dccb) ^ rm) << 4);
                uint32_t r0, r1, r2, r3;
                LDSM_X4T(r0, r1, r2, r3, addr);
                bv[2 * tp][0] = r0;     bv[2 * tp][1] = r1;
                bv[2 * tp + 1][0] = r2; bv[2 * tp + 1][1] = r3;
            }
            #pragma unroll
            for (int dt = 0; dt < 8; dt++)
                MMA16816(O[dt], pha[s], bv[dt]);
        }
    }

    // ---- epilogue: O /= l, split-pack bf16 -> a3 [ah|ah|al]
    const float inv0 = 1.0f / l0;
    const float inv1 = 1.0f / l1;
    const size_t tok0 = (size_t)(b * C_S + qt * 64 + wq * 16 + g);
    const size_t tok1 = tok0 + 8;
    #pragma unroll
    for (int t = 0; t < 8; t++) {
        const int col = h * 64 + t * 8 + qq * 2;
        uint32_t hi, lo;
        bsplit2(O[t][0] * inv0, O[t][1] * inv0, hi, lo);
        __nv_bfloat16* p0 = a3 + tok0 * K3 + col;
        *(uint32_t*)(p0)          = hi;
        *(uint32_t*)(p0 + C_E)    = hi;
        *(uint32_t*)(p0 + 2*C_E)  = lo;
        bsplit2(O[t][2] * inv1, O[t][3] * inv1, hi, lo);
        __nv_bfloat16* p1 = a3 + tok1 * K3 + col;
        *(uint32_t*)(p1)          = hi;
        *(uint32_t*)(p1 + C_E)    = hi;
        *(uint32_t*)(p1 + 2*C_E)  = lo;
    }
}

// ---------------------------------------------------------------------------
extern "C" void kernel_launch(void* const* d_in, const int* in_sizes, int n_in,
                              void* d_out, int out_size)
{
    (void)in_sizes; (void)n_in; (void)out_size;
    const float* x  = (const float*)d_in[0];
    const float* Wa = (const float*)d_in[1];
    const float* ba = (const float*)d_in[2];
    const float* Wp = (const float*)d_in[3];
    const float* bp = (const float*)d_in[4];
    float* out = (float*)d_out;

    __nv_bfloat16 *qh3, *ql3, *x3, *a3, *wa3, *wp3;
    cudaGetSymbolAddress((void**)&qh3, g_qh3);
    cudaGetSymbolAddress((void**)&ql3, g_ql3);
    cudaGetSymbolAddress((void**)&x3,  g_x3);
    cudaGetSymbolAddress((void**)&a3,  g_a3);
    cudaGetSymbolAddress((void**)&wa3, g_wa3);
    cudaGetSymbolAddress((void**)&wp3, g_wp3);

    const int smem_bytes = 2 * NSTAGE * (int)STG_BYTES;   // 96 KB
    cudaFuncSetAttribute(hgemm_bf16_kernel<0>,
                         cudaFuncAttributeMaxDynamicSharedMemorySize, smem_bytes);
    cudaFuncSetAttribute(hgemm_bf16_kernel<1>,
                         cudaFuncAttributeMaxDynamicSharedMemorySize, smem_bytes);

    // Stage 0: packing
    split_pack_kernel<<<(C_TOK * C_E / 4) / 256, 256>>>(x, x3);
    transpose_pack_kernel<<<dim3(C_3E / 32, C_E / 32), dim3(32, 8)>>>(Wa, wa3, C_3E);
    transpose_pack_kernel<<<dim3(C_E  / 32, C_E / 32), dim3(32, 8)>>>(Wp, wp3, C_E);

    // Stage 1: QKV projection -> pre-split bf16 hi/lo planes
    hgemm_bf16_kernel<1><<<dim3(C_3E / 128, C_TOK / 128), 256, smem_bytes>>>(
        x3, wa3, ba, nullptr, qh3, ql3, C_3E);

    // Stage 2: causal flash attention (tensor cores) -> packed A3
    flash_mma_kernel<<<dim3(C_S / 64, 4 * C_H), 128>>>(qh3, ql3, a3);

    // Stage 3: output projection -> fp32 out
    hgemm_bf16_kernel<0><<<dim3(C_E / 128, C_TOK / 128), 256, smem_bytes>>>(
        a3, wp3, bp, out, nullptr, nullptr, C_E);
}

// round 16
// speedup vs baseline: 1.3699x; 1.0225x over previous
#include <cuda_runtime.h>
#include <cuda_bf16.h>
#include <cstdint>

// ---------------------------------------------------------------------------
// MultiHeadAttention (B=4, S=2048, E=1024, H=16, hd=64), fp32 in/out.
// All heavy math on legacy tensor path (mma.sync.m16n8k16 bf16) with 3-term
// hi/lo splits for fp32-level accuracy:
//   GEMMs: A3=[ah|ah|al], B3=[bh|bl|bh] packed along K (K'=3072)
//   Flash: S = qh.kh + qh.kl + ql.kh ; O += ph.vh + ph.vl + pl.vh
// R12: hgemm 8 warps x 64x32, KC=64, 3-stage pipeline.
// R14: QKV pre-split to bf16 hi/lo planes in stage-1 epilogue.
// R15: flash K/V tiles via cp.async, 2-stage double buffer, 1 barrier/iter.
// ---------------------------------------------------------------------------

#define C_S   2048
#define C_E   1024
#define C_3E  3072
#define C_H   16
#define C_TOK 8192
#define K3    3072
#define KC    64
#define NCH   (K3/KC)   // 48
#define NSTAGE 3
#define STG_BYTES 16384u   // 128 rows x 128 B per operand per stage

// flash smem layout (dynamic): Q planes then 2 K/V stages
#define FL_Q_BYTES   16384u            // sQh + sQl (8KB each)
#define FL_STG_BYTES 32768u            // Kh,Kl,Vh,Vl (8KB each)
#define FL_SMEM      (FL_Q_BYTES + 2u * FL_STG_BYTES)   // 80KB

// ---------------- common helpers ----------------
__device__ __forceinline__ uint32_t smem_u32(const void* p) {
    uint32_t a;
    asm("{ .reg .u64 t; cvta.to.shared.u64 t, %1; cvt.u32.u64 %0, t; }" : "=r"(a) : "l"(p));
    return a;
}
__device__ __forceinline__ void cpa16(uint32_t s, const void* g) {
    asm volatile("cp.async.cg.shared.global [%0], [%1], 16;" :: "r"(s), "l"(g));
}
#define CP_COMMIT() asm volatile("cp.async.commit_group;" ::: "memory")
#define CP_WAIT(n)  asm volatile("cp.async.wait_group %0;" :: "n"(n) : "memory")
#define LDSM_X4(r0,r1,r2,r3,addr) \
    asm volatile("ldmatrix.sync.aligned.m8n8.x4.shared.b16 {%0,%1,%2,%3}, [%4];" \
                 : "=r"(r0),"=r"(r1),"=r"(r2),"=r"(r3) : "r"(addr))
#define LDSM_X4T(r0,r1,r2,r3,addr) \
    asm volatile("ldmatrix.sync.aligned.m8n8.x4.trans.shared.b16 {%0,%1,%2,%3}, [%4];" \
                 : "=r"(r0),"=r"(r1),"=r"(r2),"=r"(r3) : "r"(addr))
#define MMA16816(d, a, b) \
    asm volatile("mma.sync.aligned.m16n8k16.row.col.f32.bf16.bf16.f32 " \
                 "{%0,%1,%2,%3},{%4,%5,%6,%7},{%8,%9},{%0,%1,%2,%3};" \
                 : "+f"((d)[0]),"+f"((d)[1]),"+f"((d)[2]),"+f"((d)[3]) \
                 : "r"((a)[0]),"r"((a)[1]),"r"((a)[2]),"r"((a)[3]), \
                   "r"((b)[0]),"r"((b)[1]))

__device__ __forceinline__ uint32_t pkbf2(float a, float b) {
    __nv_bfloat162 h = __floats2bfloat162_rn(a, b);
    return *reinterpret_cast<uint32_t*>(&h);
}
__device__ __forceinline__ void bsplit2(float a, float b, uint32_t& hi, uint32_t& lo) {
    const __nv_bfloat16 ah = __float2bfloat16_rn(a);
    const __nv_bfloat16 bh = __float2bfloat16_rn(b);
    __nv_bfloat162 hp; hp.x = ah; hp.y = bh;
    hi = *reinterpret_cast<uint32_t*>(&hp);
    lo = pkbf2(a - __bfloat162float(ah), b - __bfloat162float(bh));
}

// ---------------- device-global scratch ----------------
__device__ __nv_bfloat16  g_qh3[(size_t)C_TOK * C_3E];   // QKV hi plane (bf16)
__device__ __nv_bfloat16  g_ql3[(size_t)C_TOK * C_3E];   // QKV lo plane (bf16)
__device__ __nv_bfloat16  g_x3[(size_t)C_TOK * K3];      // x packed   [ah|ah|al]
__device__ __nv_bfloat16  g_a3[(size_t)C_TOK * K3];      // attn out packed
__device__ __nv_bfloat16  g_wa3[(size_t)C_3E * K3];      // W_attn^T packed [bh|bl|bh]
__device__ __nv_bfloat16  g_wp3[(size_t)C_E * K3];       // W_proj^T packed

// ---------------------------------------------------------------------------
// split-pack x: fp32 [M][1024] -> bf16 [M][3072] = [ah | ah | al]
// ---------------------------------------------------------------------------
__global__ __launch_bounds__(256)
void split_pack_kernel(const float* __restrict__ in, __nv_bfloat16* __restrict__ o3)
{
    const int i4 = blockIdx.x * 256 + threadIdx.x;
    const int m  = i4 >> 8;
    const int kq = i4 & 255;
    const float4 v = *(const float4*)(in + (size_t)m * C_E + kq * 4);
    uint32_t h0, l0, h1, l1;
    bsplit2(v.x, v.y, h0, l0);
    bsplit2(v.z, v.w, h1, l1);
    uint2 hh = make_uint2(h0, h1);
    uint2 ll = make_uint2(l0, l1);
    __nv_bfloat16* base = o3 + (size_t)m * K3 + kq * 4;
    *(uint2*)(base)          = hh;
    *(uint2*)(base + C_E)    = hh;
    *(uint2*)(base + 2*C_E)  = ll;
}

// ---------------------------------------------------------------------------
// transpose + split-pack W[K=1024][N] -> Wt3[N][3072] = [bh | bl | bh]
// ---------------------------------------------------------------------------
__global__ __launch_bounds__(256)
void transpose_pack_kernel(const float* __restrict__ W, __nv_bfloat16* __restrict__ T3, int N)
{
    __shared__ float t[32][33];
    const int tx = threadIdx.x, ty = threadIdx.y;
    const int n0 = blockIdx.x * 32, k0 = blockIdx.y * 32;
    #pragma unroll
    for (int i = 0; i < 4; i++)
        t[ty + i * 8][tx] = W[(size_t)(k0 + ty + i * 8) * N + n0 + tx];
    __syncthreads();
    #pragma unroll
    for (int i = 0; i < 4; i++) {
        const float v = t[tx][ty + i * 8];
        const __nv_bfloat16 bh = __float2bfloat16_rn(v);
        const __nv_bfloat16 bl = __float2bfloat16_rn(v - __bfloat162float(bh));
        __nv_bfloat16* base = T3 + (size_t)(n0 + ty + i * 8) * K3 + k0 + tx;
        base[0]       = bh;
        base[C_E]     = bl;
        base[2*C_E]   = bh;
    }
}

// ---------------------------------------------------------------------------
// bf16 HGEMM: C = A3 @ B3^T + bias. CTA 128x128, 8 warps x (64x32) warp tiles,
// K-chunk 64, 3-stage cp.async pipeline, ONE __syncthreads per chunk.
// smem row = 128B (8x16B chunks), chunk cc stored at cc^(r&7).
// OUT_SPLIT=0: fp32 C.  OUT_SPLIT=1: bf16 hi/lo planes (for flash input).
// ---------------------------------------------------------------------------
template <int OUT_SPLIT>
__global__ __launch_bounds__(256, 2)
void hgemm_bf16_kernel(const __nv_bfloat16* __restrict__ A3,
                       const __nv_bfloat16* __restrict__ B3,
                       const float* __restrict__ bias,
                       float* __restrict__ C,
                       __nv_bfloat16* __restrict__ OH,
                       __nv_bfloat16* __restrict__ OL,
                       int N)
{
    extern __shared__ __align__(16) unsigned char dsm[];
    __shared__ float bias_s[128];

    const int t    = threadIdx.x;
    const int lane = t & 31;
    const int wid  = t >> 5;
    const int bm   = blockIdx.y * 128;
    const int bn   = blockIdx.x * 128;
    const int wm   = (wid & 1) * 64;
    const int wn   = (wid >> 1) * 32;

    if (t < 128) bias_s[t] = bias[bn + t];

    const uint32_t sa = smem_u32(dsm);
    const uint32_t sb = sa + NSTAGE * STG_BYTES;

    const int fr   = t >> 1;
    const int half = t & 1;
    uint32_t so[4];
    #pragma unroll
    for (int j = 0; j < 4; j++)
        so[j] = (uint32_t)fr * 128u + (uint32_t)(((half * 4 + j) ^ (fr & 7)) << 4);
    const __nv_bfloat16* gA = A3 + (size_t)(bm + fr) * K3 + half * 32;
    const __nv_bfloat16* gB = B3 + (size_t)(bn + fr) * K3 + half * 32;

    const int lr = lane & 7;
    const int ccA = (lane >> 4) & 1;
    const int ahalf = (lane >> 3) & 1;
    const int ccB = (lane >> 3) & 1;
    const int bhalf = (lane >> 4) & 1;
    uint32_t offA[4]; int rm7A[4];
    #pragma unroll
    for (int i = 0; i < 4; i++) {
        const int r = wm + i * 16 + ahalf * 8 + lr;
        offA[i] = (uint32_t)r * 128u; rm7A[i] = r & 7;
    }
    uint32_t offB[2]; int rm7B[2];
    #pragma unroll
    for (int j = 0; j < 2; j++) {
        const int r = wn + j * 16 + bhalf * 8 + lr;
        offB[j] = (uint32_t)r * 128u; rm7B[j] = r & 7;
    }

    float acc[4][4][4];
    #pragma unroll
    for (int i = 0; i < 4; i++)
        #pragma unroll
        for (int n = 0; n < 4; n++)
            #pragma unroll
            for (int k = 0; k < 4; k++) acc[i][n][k] = 0.f;

    #pragma unroll
    for (int p = 0; p < NSTAGE - 1; p++) {
        const uint32_t d = (uint32_t)p * STG_BYTES;
        #pragma unroll
        for (int j = 0; j < 4; j++) {
            cpa16(sa + d + so[j], gA + p * KC + j * 8);
            cpa16(sb + d + so[j], gB + p * KC + j * 8);
        }
        CP_COMMIT();
    }

    int stage = 0;
    for (int c = 0; c < NCH; c++) {
        CP_WAIT(NSTAGE - 2);
        __syncthreads();
        if (c + NSTAGE - 1 < NCH) {
            int ps = stage + (NSTAGE - 1); if (ps >= NSTAGE) ps -= NSTAGE;
            const uint32_t d = (uint32_t)ps * STG_BYTES;
            #pragma unroll
            for (int j = 0; j < 4; j++) {
                cpa16(sa + d + so[j], gA + (c + NSTAGE - 1) * KC + j * 8);
                cpa16(sb + d + so[j], gB + (c + NSTAGE - 1) * KC + j * 8);
            }
        }
        CP_COMMIT();

        const uint32_t ab = sa + (uint32_t)stage * STG_BYTES;
        const uint32_t bb = sb + (uint32_t)stage * STG_BYTES;
        #pragma unroll
        for (int s = 0; s < 4; s++) {
            uint32_t a[4][4];
            #pragma unroll
            for (int i = 0; i < 4; i++) {
                const uint32_t addr = ab + offA[i] +
                    (uint32_t)((((s << 1) | ccA) ^ rm7A[i]) << 4);
                LDSM_X4(a[i][0], a[i][1], a[i][2], a[i][3], addr);
            }
            uint32_t bfr[4][2];
            #pragma unroll
            for (int j = 0; j < 2; j++) {
                const uint32_t addr = bb + offB[j] +
                    (uint32_t)((((s << 1) | ccB) ^ rm7B[j]) << 4);
                uint32_t r0, r1, r2, r3;
                LDSM_X4(r0, r1, r2, r3, addr);
                bfr[2 * j][0] = r0;     bfr[2 * j][1] = r1;
                bfr[2 * j + 1][0] = r2; bfr[2 * j + 1][1] = r3;
            }
            #pragma unroll
            for (int i = 0; i < 4; i++)
                #pragma unroll
                for (int n = 0; n < 4; n++)
                    MMA16816(acc[i][n], a[i], bfr[n]);
        }
        if (++stage >= NSTAGE) stage = 0;
    }

    __syncthreads();
    #pragma unroll
    for (int i = 0; i < 4; i++) {
        const int row0 = bm + wm + i * 16 + (lane >> 2);
        #pragma unroll
        for (int n = 0; n < 4; n++) {
            const int lcol = wn + n * 8 + (lane & 3) * 2;
            const int col  = bn + lcol;
            const float b0 = bias_s[lcol], b1 = bias_s[lcol + 1];
            if (OUT_SPLIT == 0) {
                float2 v0 = make_float2(acc[i][n][0] + b0, acc[i][n][1] + b1);
                float2 v1 = make_float2(acc[i][n][2] + b0, acc[i][n][3] + b1);
                *(float2*)(C + (size_t)row0 * N + col)       = v0;
                *(float2*)(C + (size_t)(row0 + 8) * N + col) = v1;
            } else {
                uint32_t h, l;
                bsplit2(acc[i][n][0] + b0, acc[i][n][1] + b1, h, l);
                *(uint32_t*)(OH + (size_t)row0 * N + col) = h;
                *(uint32_t*)(OL + (size_t)row0 * N + col) = l;
                bsplit2(acc[i][n][2] + b0, acc[i][n][3] + b1, h, l);
                *(uint32_t*)(OH + (size_t)(row0 + 8) * N + col) = h;
                *(uint32_t*)(OL + (size_t)(row0 + 8) * N + col) = l;
            }
        }
    }
}

// ---------------------------------------------------------------------------
// Flash attention on tensor cores (FA2-style). Block = 128 thr (4 warps),
// each warp owns 16 q-rows of a 64-row q-tile. Q/K/V arrive PRE-SPLIT as
// bf16 hi/lo planes. K/V tiles stream through a 2-stage cp.async double
// buffer: ONE barrier per iteration, loads fully overlapped with compute.
// smem rows = 128B (8 chunks), chunk cc stored at cc^(r&7).
// ---------------------------------------------------------------------------
__global__ __launch_bounds__(128, 2)
void flash_mma_kernel(const __nv_bfloat16* __restrict__ qh3,
                      const __nv_bfloat16* __restrict__ ql3,
                      __nv_bfloat16* __restrict__ a3)
{
    extern __shared__ __align__(16) unsigned char fdsm[];

    const int qt  = (int)gridDim.x - 1 - (int)blockIdx.x;
    const int bh  = blockIdx.y;
    const int b   = bh >> 4;
    const int h   = bh & 15;
    const int tid = threadIdx.x;
    const int lane = tid & 31;
    const int wq   = tid >> 5;

    const size_t rowbase = (size_t)b * C_S * C_3E + h * 64;
    const __nv_bfloat16* Qh = qh3 + rowbase;
    const __nv_bfloat16* Ql = ql3 + rowbase;
    const __nv_bfloat16* Kh = Qh + C_E;
    const __nv_bfloat16* Kl = Ql + C_E;
    const __nv_bfloat16* Vh = Qh + 2 * C_E;
    const __nv_bfloat16* Vl = Ql + 2 * C_E;

    const uint32_t sbase = smem_u32(fdsm);
    const uint32_t bQh = sbase, bQl = sbase + 8192u;

    // per-thread K/V fill chunks (4 per plane)
    int fr_[4]; uint32_t foff[4];
    #pragma unroll
    for (int it = 0; it < 4; it++) {
        const int ch = it * 128 + tid;
        const int r  = ch >> 3;
        const int cc = ch & 7;
        fr_[it]  = r;
        foff[it] = r * 128u + (uint32_t)((cc ^ (r & 7)) << 4);
    }
    const int fcc8[4] = { (tid & 7) * 8, ((128 + tid) & 7) * 8,
                          ((256 + tid) & 7) * 8, ((384 + tid) & 7) * 8 };

    // ---- load Q tile (pre-split planes) + prologue prefetch of kt=0
    #pragma unroll
    for (int it = 0; it < 4; it++) {
        const size_t go = (size_t)(qt * 64 + fr_[it]) * C_3E + fcc8[it];
        *(uint4*)((char*)fdsm + foff[it]) = *(const uint4*)(Qh + go);
        *(uint4*)((char*)fdsm + 8192u + foff[it]) = *(const uint4*)(Ql + go);
    }
    {   // prefetch kt=0 into stage 0
        const uint32_t stg = sbase + FL_Q_BYTES;
        #pragma unroll
        for (int it = 0; it < 4; it++) {
            const size_t go = (size_t)(0 * 64 + fr_[it]) * C_3E + fcc8[it];
            cpa16(stg           + foff[it], Kh + go);
            cpa16(stg +  8192u  + foff[it], Kl + go);
            cpa16(stg + 16384u  + foff[it], Vh + go);
            cpa16(stg + 24576u  + foff[it], Vl + go);
        }
        CP_COMMIT();
    }
    __syncthreads();

    // ---- build Q A-fragments in registers (persist whole kernel)
    uint32_t qhf[4][4], qlf[4][4];
    {
        const int arow = wq * 16 + ((lane >> 3) & 1) * 8 + (lane & 7);
        const uint32_t ro = (uint32_t)arow * 128u;
        const int rm = arow & 7;
        const int cca = (lane >> 4) & 1;
        #pragma unroll
        for (int ks = 0; ks < 4; ks++) {
            const uint32_t co = (uint32_t)(((ks * 2 + cca) ^ rm) << 4);
            LDSM_X4(qhf[ks][0], qhf[ks][1], qhf[ks][2], qhf[ks][3], bQh + ro + co);
            LDSM_X4(qlf[ks][0], qlf[ks][1], qlf[ks][2], qlf[ks][3], bQl + ro + co);
        }
    }

    const int g  = lane >> 2;
    const int qq = lane & 3;
    float m0 = -1e30f, m1 = -1e30f, l0 = 0.f, l1 = 0.f;
    float O[8][4];
    #pragma unroll
    for (int dt = 0; dt < 8; dt++)
        #pragma unroll
        for (int k = 0; k < 4; k++) O[dt][k] = 0.f;

    for (int kt = 0; kt <= qt; kt++) {
        const uint32_t stg = sbase + FL_Q_BYTES + (uint32_t)(kt & 1) * FL_STG_BYTES;
        const uint32_t bKh = stg, bKl = stg + 8192u;
        const uint32_t bVh = stg + 16384u, bVl = stg + 24576u;

        CP_WAIT(0);
        __syncthreads();   // stage (kt&1) ready; other stage free (read in kt-1)

        if (kt + 1 <= qt) {   // overlap next tile load with this compute
            const uint32_t nst = sbase + FL_Q_BYTES + (uint32_t)((kt + 1) & 1) * FL_STG_BYTES;
            #pragma unroll
            for (int it = 0; it < 4; it++) {
                const size_t go = (size_t)((kt + 1) * 64 + fr_[it]) * C_3E + fcc8[it];
                cpa16(nst           + foff[it], Kh + go);
                cpa16(nst +  8192u  + foff[it], Kl + go);
                cpa16(nst + 16384u  + foff[it], Vh + go);
                cpa16(nst + 24576u  + foff[it], Vl + go);
            }
            CP_COMMIT();
        }

        // ---- S = Q.K^T  (3 passes: qh.kh, qh.kl, ql.kh)
        float S[8][4];
        #pragma unroll
        for (int nt = 0; nt < 8; nt++)
            #pragma unroll
            for (int k = 0; k < 4; k++) S[nt][k] = 0.f;

        const int brow_h = ((lane >> 4) & 1) * 8 + (lane & 7);
        const int ccb    = (lane >> 3) & 1;
        #pragma unroll
        for (int pass = 0; pass < 3; pass++) {
            const uint32_t kb = (pass == 1) ? bKl : bKh;
            uint32_t (*af)[4] = (pass == 2) ? qlf : qhf;
            #pragma unroll
            for (int ks = 0; ks < 4; ks++) {
                #pragma unroll
                for (int tp = 0; tp < 4; tp++) {
                    const int brow = tp * 16 + brow_h;
                    const uint32_t addr = kb + (uint32_t)brow * 128u +
                        (uint32_t)((((ks * 2 + ccb)) ^ (brow & 7)) << 4);
                    uint32_t r0, r1, r2, r3;
                    LDSM_X4(r0, r1, r2, r3, addr);
                    uint32_t b0[2] = { r0, r1 };
                    uint32_t b1[2] = { r2, r3 };
                    MMA16816(S[2 * tp],     af[ks], b0);
                    MMA16816(S[2 * tp + 1], af[ks], b1);
                }
            }
        }

        // ---- masked online softmax on fragments
        const bool diag = (kt == qt);
        const int r0l = wq * 16 + g;
        const int r1l = r0l + 8;
        float pv[8][4];
        float mx0 = -1e30f, mx1 = -1e30f;
        #pragma unroll
        for (int t = 0; t < 8; t++) {
            const int c0 = t * 8 + qq * 2;
            float s0 = S[t][0] * 0.125f;
            float s1 = S[t][1] * 0.125f;
            float s2 = S[t][2] * 0.125f;
            float s3 = S[t][3] * 0.125f;
            if (diag) {
                if (c0     > r0l) s0 = -1e30f;
                if (c0 + 1 > r0l) s1 = -1e30f;
                if (c0     > r1l) s2 = -1e30f;
                if (c0 + 1 > r1l) s3 = -1e30f;
            }
            pv[t][0] = s0; pv[t][1] = s1; pv[t][2] = s2; pv[t][3] = s3;
            mx0 = fmaxf(mx0, fmaxf(s0, s1));
            mx1 = fmaxf(mx1, fmaxf(s2, s3));
        }
        mx0 = fmaxf(mx0, __shfl_xor_sync(0xffffffffu, mx0, 1));
        mx0 = fmaxf(mx0, __shfl_xor_sync(0xffffffffu, mx0, 2));
        mx1 = fmaxf(mx1, __shfl_xor_sync(0xffffffffu, mx1, 1));
        mx1 = fmaxf(mx1, __shfl_xor_sync(0xffffffffu, mx1, 2));
        const float mn0 = fmaxf(m0, mx0);
        const float mn1 = fmaxf(m1, mx1);
        const float al0 = __expf(m0 - mn0);
        const float al1 = __expf(m1 - mn1);
        m0 = mn0; m1 = mn1;
        float sum0 = 0.f, sum1 = 0.f;
        #pragma unroll
        for (int t = 0; t < 8; t++) {
            const float p0 = __expf(pv[t][0] - mn0);
            const float p1 = __expf(pv[t][1] - mn0);
            const float p2 = __expf(pv[t][2] - mn1);
            const float p3 = __expf(pv[t][3] - mn1);
            pv[t][0] = p0; pv[t][1] = p1; pv[t][2] = p2; pv[t][3] = p3;
            sum0 += p0 + p1;
            sum1 += p2 + p3;
        }
        sum0 += __shfl_xor_sync(0xffffffffu, sum0, 1);
        sum0 += __shfl_xor_sync(0xffffffffu, sum0, 2);
        sum1 += __shfl_xor_sync(0xffffffffu, sum1, 1);
        sum1 += __shfl_xor_sync(0xffffffffu, sum1, 2);
        l0 = l0 * al0 + sum0;
        l1 = l1 * al1 + sum1;

        // ---- P fragments (acc layout == A-operand layout; hi/lo split)
        uint32_t pha[4][4], pla[4][4];
        #pragma unroll
        for (int s = 0; s < 4; s++) {
            bsplit2(pv[2 * s][0],     pv[2 * s][1],     pha[s][0], pla[s][0]);
            bsplit2(pv[2 * s][2],     pv[2 * s][3],     pha[s][1], pla[s][1]);
            bsplit2(pv[2 * s + 1][0], pv[2 * s + 1][1], pha[s][2], pla[s][2]);
            bsplit2(pv[2 * s + 1][2], pv[2 * s + 1][3], pha[s][3], pla[s][3]);
        }

        // ---- rescale O by alpha
        #pragma unroll
        for (int dt = 0; dt < 8; dt++) {
            O[dt][0] *= al0; O[dt][1] *= al0;
            O[dt][2] *= al1; O[dt][3] *= al1;
        }

        // ---- O += P.V  (passes: ph.vh, pl.vh, ph.vl)
        const int jrow_h = ((lane >> 3) & 1) * 8 + (lane & 7);
        const int dccb   = (lane >> 4) & 1;
        #pragma unroll
        for (int s = 0; s < 4; s++) {
            const int jrow = s * 16 + jrow_h;
            const uint32_t rbase = (uint32_t)jrow * 128u;
            const int rm = jrow & 7;
            uint32_t bv[8][2];
            #pragma unroll
            for (int tp = 0; tp < 4; tp++) {
                const uint32_t addr = bVh + rbase +
                    (uint32_t)(((tp * 2 + dccb) ^ rm) << 4);
                uint32_t r0, r1, r2, r3;
                LDSM_X4T(r0, r1, r2, r3, addr);
                bv[2 * tp][0] = r0;     bv[2 * tp][1] = r1;
                bv[2 * tp + 1][0] = r2; bv[2 * tp + 1][1] = r3;
            }
            #pragma unroll
            for (int dt = 0; dt < 8; dt++) {
                MMA16816(O[dt], pha[s], bv[dt]);
                MMA16816(O[dt], pla[s], bv[dt]);
            }
            #pragma unroll
            for (int tp = 0; tp < 4; tp++) {
                const uint32_t addr = bVl + rbase +
                    (uint32_t)(((tp * 2 + dccb) ^ rm) << 4);
                uint32_t r0, r1, r2, r3;
                LDSM_X4T(r0, r1, r2, r3, addr);
                bv[2 * tp][0] = r0;     bv[2 * tp][1] = r1;
                bv[2 * tp + 1][0] = r2; bv[2 * tp + 1][1] = r3;
            }
            #pragma unroll
            for (int dt = 0; dt < 8; dt++)
                MMA16816(O[dt], pha[s], bv[dt]);
        }
        __syncthreads();   // all warps done reading stage (kt&1) before it is
                           // refilled at kt+2 (prefetch issued at top of kt+1)
    }

    // ---- epilogue: O /= l, split-pack bf16 -> a3 [ah|ah|al]
    const float inv0 = 1.0f / l0;
    const float inv1 = 1.0f / l1;
    const size_t tok0 = (size_t)(b * C_S + qt * 64 + wq * 16 + g);
    const size_t tok1 = tok0 + 8;
    #pragma unroll
    for (int t = 0; t < 8; t++) {
        const int col = h * 64 + t * 8 + qq * 2;
        uint32_t hi, lo;
        bsplit2(O[t][0] * inv0, O[t][1] * inv0, hi, lo);
        __nv_bfloat16* p0 = a3 + tok0 * K3 + col;
        *(uint32_t*)(p0)          = hi;
        *(uint32_t*)(p0 + C_E)    = hi;
        *(uint32_t*)(p0 + 2*C_E)  = lo;
        bsplit2(O[t][2] * inv1, O[t][3] * inv1, hi, lo);
        __nv_bfloat16* p1 = a3 + tok1 * K3 + col;
        *(uint32_t*)(p1)          = hi;
        *(uint32_t*)(p1 + C_E)    = hi;
        *(uint32_t*)(p1 + 2*C_E)  = lo;
    }
}

// ---------------------------------------------------------------------------
extern "C" void kernel_launch(void* const* d_in, const int* in_sizes, int n_in,
                              void* d_out, int out_size)
{
    (void)in_sizes; (void)n_in; (void)out_size;
    const float* x  = (const float*)d_in[0];
    const float* Wa = (const float*)d_in[1];
    const float* ba = (const float*)d_in[2];
    const float* Wp = (const float*)d_in[3];
    const float* bp = (const float*)d_in[4];
    float* out = (float*)d_out;

    __nv_bfloat16 *qh3, *ql3, *x3, *a3, *wa3, *wp3;
    cudaGetSymbolAddress((void**)&qh3, g_qh3);
    cudaGetSymbolAddress((void**)&ql3, g_ql3);
    cudaGetSymbolAddress((void**)&x3,  g_x3);
    cudaGetSymbolAddress((void**)&a3,  g_a3);
    cudaGetSymbolAddress((void**)&wa3, g_wa3);
    cudaGetSymbolAddress((void**)&wp3, g_wp3);

    const int smem_bytes = 2 * NSTAGE * (int)STG_BYTES;   // 96 KB
    cudaFuncSetAttribute(hgemm_bf16_kernel<0>,
                         cudaFuncAttributeMaxDynamicSharedMemorySize, smem_bytes);
    cudaFuncSetAttribute(hgemm_bf16_kernel<1>,
                         cudaFuncAttributeMaxDynamicSharedMemorySize, smem_bytes);
    cudaFuncSetAttribute(flash_mma_kernel,
                         cudaFuncAttributeMaxDynamicSharedMemorySize, (int)FL_SMEM);

    // Stage 0: packing
    split_pack_kernel<<<(C_TOK * C_E / 4) / 256, 256>>>(x, x3);
    transpose_pack_kernel<<<dim3(C_3E / 32, C_E / 32), dim3(32, 8)>>>(Wa, wa3, C_3E);
    transpose_pack_kernel<<<dim3(C_E  / 32, C_E / 32), dim3(32, 8)>>>(Wp, wp3, C_E);

    // Stage 1: QKV projection -> pre-split bf16 hi/lo planes
    hgemm_bf16_kernel<1><<<dim3(C_3E / 128, C_TOK / 128), 256, smem_bytes>>>(
        x3, wa3, ba, nullptr, qh3, ql3, C_3E);

    // Stage 2: causal flash attention (cp.async double-buffered) -> packed A3
    flash_mma_kernel<<<dim3(C_S / 64, 4 * C_H), 128, FL_SMEM>>>(qh3, ql3, a3);

    // Stage 3: output projection -> fp32 out
    hgemm_bf16_kernel<0><<<dim3(C_E / 128, C_TOK / 128), 256, smem_bytes>>>(
        a3, wp3, bp, out, nullptr, nullptr, C_E);
}